// round 1
// baseline (speedup 1.0000x reference)
#include <cuda_runtime.h>
#include <math.h>

// Problem constants
#define BSZ   4096        // B*S tokens
#define HD    1024        // hidden
#define NE    16          // experts
#define TOPK  2
#define CAPM  768         // CAP_MAX
#define HI2   512         // H/2

static const long long D_SZ    = (long long)BSZ * NE * CAPM;       // 50331648
static const long long COMB_OFF= D_SZ;
static const long long RP_OFF  = 2 * D_SZ;                         // 100663296
static const long long AUX_OFF = RP_OFF + (long long)BSZ * NE;     // 100728832
static const long long IMP_OFF = AUX_OFF + 1;                      // 100728833

// Scratch (device globals; no cudaMalloc allowed)
__device__ float g_H1[(size_t)BSZ * HD];     // relu(X@W1+b1)   16MB
__device__ float g_Hi[(size_t)BSZ * HI2];    // relu(X@Wi1+bi1)  8MB
__device__ float g_avg[HD];                  // column sums of X
__device__ float g_impsum;                   // sum of importance
__device__ float g_probsum[NE];              // sum of router probs per expert
__device__ float g_tp[BSZ * 2];              // top-2 probs
__device__ int   g_te[BSZ * 2];              // top-2 expert ids
__device__ int   g_k;                        // adaptive_k in {1,2}

// ---------------------------------------------------------------------------
// zero the whole output buffer (poisoned by harness)
__global__ void zero_out_kernel(float* __restrict__ out, long long n) {
    long long stride = (long long)gridDim.x * blockDim.x;
    long long i = (long long)blockIdx.x * blockDim.x + threadIdx.x;
    long long n4 = n >> 2;
    float4 z = make_float4(0.f, 0.f, 0.f, 0.f);
    for (long long j = i; j < n4; j += stride)
        ((float4*)out)[j] = z;
    if (i < (n & 3LL))
        out[(n4 << 2) + i] = 0.f;
}

// zero small accumulators
__global__ void init_small_kernel() {
    int t = threadIdx.x;
    if (t < HD) g_avg[t] = 0.f;
    if (t < NE) g_probsum[t] = 0.f;
    if (t == 0) g_impsum = 0.f;
}

// ---------------------------------------------------------------------------
// C[M,N] = relu(A[M,K] @ W[K,N] + bias[N]); 64x64 tile, 4x4 per thread.
__global__ __launch_bounds__(256)
void gemm_bias_relu(const float* __restrict__ A, const float* __restrict__ W,
                    const float* __restrict__ bias, float* __restrict__ C,
                    int M, int N, int K) {
    __shared__ float As[64][16];
    __shared__ float Ws[16][64];
    const int tx = threadIdx.x, ty = threadIdx.y;
    const int tid = ty * 16 + tx;
    const int m0 = blockIdx.y * 64;
    const int n0 = blockIdx.x * 64;

    const int la_m = tid >> 2;            // 0..63
    const int la_k = (tid & 3) << 2;      // 0,4,8,12
    const int lw_k = tid >> 4;            // 0..15
    const int lw_n = (tid & 15) << 2;     // 0..60

    float acc[4][4];
#pragma unroll
    for (int i = 0; i < 4; i++)
#pragma unroll
        for (int j = 0; j < 4; j++) acc[i][j] = 0.f;

    for (int kk = 0; kk < K; kk += 16) {
        float4 av = *(const float4*)(A + (size_t)(m0 + la_m) * K + kk + la_k);
        *(float4*)&As[la_m][la_k] = av;
        float4 wv = *(const float4*)(W + (size_t)(kk + lw_k) * N + n0 + lw_n);
        *(float4*)&Ws[lw_k][lw_n] = wv;
        __syncthreads();
#pragma unroll
        for (int k = 0; k < 16; k++) {
            float a0 = As[ty * 4 + 0][k];
            float a1 = As[ty * 4 + 1][k];
            float a2 = As[ty * 4 + 2][k];
            float a3 = As[ty * 4 + 3][k];
            float4 b = *(float4*)&Ws[k][tx * 4];
            acc[0][0] += a0 * b.x; acc[0][1] += a0 * b.y; acc[0][2] += a0 * b.z; acc[0][3] += a0 * b.w;
            acc[1][0] += a1 * b.x; acc[1][1] += a1 * b.y; acc[1][2] += a1 * b.z; acc[1][3] += a1 * b.w;
            acc[2][0] += a2 * b.x; acc[2][1] += a2 * b.y; acc[2][2] += a2 * b.z; acc[2][3] += a2 * b.w;
            acc[3][0] += a3 * b.x; acc[3][1] += a3 * b.y; acc[3][2] += a3 * b.z; acc[3][3] += a3 * b.w;
        }
        __syncthreads();
    }

#pragma unroll
    for (int i = 0; i < 4; i++) {
        int row = m0 + ty * 4 + i;
#pragma unroll
        for (int j = 0; j < 4; j++) {
            int col = n0 + tx * 4 + j;
            float v = acc[i][j] + bias[col];
            C[(size_t)row * N + col] = fmaxf(v, 0.f);
        }
    }
}

// ---------------------------------------------------------------------------
// importance = sigmoid(Hi @ Wi2 + bi2); one warp per token
__global__ __launch_bounds__(256)
void imp_kernel(const float* __restrict__ Wi2, const float* __restrict__ bi2,
                float* __restrict__ out_imp) {
    __shared__ float w[HI2];
    int t = threadIdx.x;
    w[t] = Wi2[t];
    w[t + 256] = Wi2[t + 256];
    __syncthreads();
    int warp = t >> 5, lane = t & 31;
    int token = blockIdx.x * 8 + warp;
    const float* h = g_Hi + (size_t)token * HI2;
    float acc = 0.f;
#pragma unroll
    for (int i = 0; i < HI2 / 32; i++)
        acc += h[lane + 32 * i] * w[lane + 32 * i];
#pragma unroll
    for (int o = 16; o; o >>= 1) acc += __shfl_xor_sync(0xffffffffu, acc, o);
    if (lane == 0) {
        float v = 1.f / (1.f + expf(-(acc + bi2[0])));
        out_imp[token] = v;
        atomicAdd(&g_impsum, v);
    }
}

// column sums of X -> g_avg (divide by 4096 later)
__global__ __launch_bounds__(256)
void colmean_kernel(const float* __restrict__ X) {
    int t = threadIdx.x;
    int r0 = blockIdx.x * 64;
    float4 s = make_float4(0.f, 0.f, 0.f, 0.f);
    for (int r = r0; r < r0 + 64; r++) {
        float4 v = ((const float4*)X)[(size_t)r * 256 + t];
        s.x += v.x; s.y += v.y; s.z += v.z; s.w += v.w;
    }
    atomicAdd(&g_avg[t * 4 + 0], s.x);
    atomicAdd(&g_avg[t * 4 + 1], s.y);
    atomicAdd(&g_avg[t * 4 + 2], s.z);
    atomicAdd(&g_avg[t * 4 + 3], s.w);
}

// tiny top-k predictor net -> g_k
__global__ __launch_bounds__(256)
void tk_kernel(const float* __restrict__ Wt1, const float* __restrict__ bt1,
               const float* __restrict__ Wt2, const float* __restrict__ bt2) {
    int j = threadIdx.x;  // 256 hidden units
    const float invN = 1.f / 4096.f;
    float acc = bt1[j];
    for (int i = 0; i < HD; i++)
        acc += (g_avg[i] * invN) * Wt1[(size_t)i * 256 + j];
    acc += (g_impsum * invN) * Wt1[(size_t)HD * 256 + j];
    float h = fmaxf(acc, 0.f);
    __shared__ float s0[256], s1[256];
    s0[j] = h * Wt2[j * 2 + 0];
    s1[j] = h * Wt2[j * 2 + 1];
    __syncthreads();
    for (int o = 128; o; o >>= 1) {
        if (j < o) { s0[j] += s0[j + o]; s1[j] += s1[j + o]; }
        __syncthreads();
    }
    if (j == 0) {
        float l0 = s0[0] + bt2[0];
        float l1 = s1[0] + bt2[1];
        g_k = (l1 > l0) ? 2 : 1;   // argmax keeps lower index on tie
    }
}

// ---------------------------------------------------------------------------
// router: logits = H1 @ W2 + b2 -> softmax -> probs + top-2. One warp/token.
__global__ __launch_bounds__(256)
void router_kernel(const float* __restrict__ W2, const float* __restrict__ b2,
                   float* __restrict__ out_rp) {
    __shared__ float ps[NE];
    int t = threadIdx.x, warp = t >> 5, lane = t & 31;
    if (t < NE) ps[t] = 0.f;
    __syncthreads();
    int token = blockIdx.x * 8 + warp;
    const float* h = g_H1 + (size_t)token * HD;
    float acc[NE];
#pragma unroll
    for (int e = 0; e < NE; e++) acc[e] = 0.f;
    for (int i = 0; i < HD / 32; i++) {
        int k = lane + 32 * i;
        float hv = h[k];
        const float4* w = (const float4*)(W2 + (size_t)k * NE);
        float4 w0 = __ldg(w + 0), w1 = __ldg(w + 1), w2 = __ldg(w + 2), w3 = __ldg(w + 3);
        acc[0]  += hv * w0.x; acc[1]  += hv * w0.y; acc[2]  += hv * w0.z; acc[3]  += hv * w0.w;
        acc[4]  += hv * w1.x; acc[5]  += hv * w1.y; acc[6]  += hv * w1.z; acc[7]  += hv * w1.w;
        acc[8]  += hv * w2.x; acc[9]  += hv * w2.y; acc[10] += hv * w2.z; acc[11] += hv * w2.w;
        acc[12] += hv * w3.x; acc[13] += hv * w3.y; acc[14] += hv * w3.z; acc[15] += hv * w3.w;
    }
#pragma unroll
    for (int e = 0; e < NE; e++)
#pragma unroll
        for (int o = 16; o; o >>= 1) acc[e] += __shfl_xor_sync(0xffffffffu, acc[e], o);

    if (lane == 0) {
        float p[NE];
        float mx = -1e30f;
#pragma unroll
        for (int e = 0; e < NE; e++) { p[e] = acc[e] + b2[e]; mx = fmaxf(mx, p[e]); }
        float sum = 0.f;
#pragma unroll
        for (int e = 0; e < NE; e++) { p[e] = expf(p[e] - mx); sum += p[e]; }
        float inv = 1.f / sum;
#pragma unroll
        for (int e = 0; e < NE; e++) p[e] *= inv;
#pragma unroll
        for (int e = 0; e < NE; e++) {
            out_rp[(size_t)token * NE + e] = p[e];
            atomicAdd(&ps[e], p[e]);
        }
        // top-1: strict > keeps lowest index (matches jax.lax.top_k stability)
        int e0 = 0;
#pragma unroll
        for (int e = 1; e < NE; e++) if (p[e] > p[e0]) e0 = e;
        int e1 = (e0 == 0) ? 1 : 0;
#pragma unroll
        for (int e = 0; e < NE; e++)
            if (e != e0 && e != e1 && p[e] > p[e1]) e1 = e;
        // ensure e1 is the best among e != e0 with lowest-index tie-break:
        // redo carefully (initial seed may not be lowest-index max)
        int best = -1; float bv = -1.f;
#pragma unroll
        for (int e = 0; e < NE; e++) {
            if (e == e0) continue;
            if (p[e] > bv) { bv = p[e]; best = e; }
        }
        e1 = best;
        g_tp[token * 2 + 0] = p[e0];
        g_tp[token * 2 + 1] = p[e1];
        g_te[token * 2 + 0] = e0;
        g_te[token * 2 + 1] = e1;
    }
    __syncthreads();
    if (t < NE) atomicAdd(&g_probsum[t], ps[t]);
}

// ---------------------------------------------------------------------------
// single-block order-preserving per-expert scan + scatter + aux loss
__global__ __launch_bounds__(256)
void scan_scatter_kernel(float* __restrict__ out) {
    __shared__ int sh[256 * NE];
    __shared__ int totals[NE];
    int t = threadIdx.x;
    int k = g_k;
    int cap = 384 * k;   // floor(4096*1.5*k/16)
    int base = t * 32;   // 32 assignments per thread, N = 8192

#pragma unroll
    for (int e = 0; e < NE; e++) sh[t * NE + e] = 0;
    // pass 1: local counts of valid assignments per expert (in order)
    for (int i = 0; i < 32; i++) {
        int n = base + i;
        int slot = n & 1;
        if (slot < k) {
            int e = g_te[n];
            sh[t * NE + e]++;
        }
    }
    __syncthreads();
    // exclusive prefix across threads, one thread per expert
    if (t < NE) {
        int run = 0;
        for (int i = 0; i < 256; i++) {
            int c = sh[i * NE + t];
            sh[i * NE + t] = run;
            run += c;
        }
        totals[t] = run;
    }
    __syncthreads();

    float* disp = out;
    float* comb = out + COMB_OFF;
    const float* imp = out + IMP_OFF;

    // pass 2: replay, compute positions, scatter writes
    for (int i = 0; i < 32; i++) {
        int n = base + i;
        int token = n >> 1;
        int slot = n & 1;
        if (slot >= k) continue;
        int e = g_te[n];
        int pos = sh[t * NE + e]++;
        if (pos < cap) {
            float tp0 = g_tp[token * 2 + 0];
            float tp1 = g_tp[token * 2 + 1];
            float denom = (k == 2) ? (tp0 + tp1 + 1e-8f) : (tp0 + 1e-8f);
            float pn = ((slot == 0) ? tp0 : tp1) / denom;
            float f = 1.f + ((imp[token] > 0.5f) ? 1.f : 0.f);
            long long off = (long long)token * NE * CAPM + (long long)e * CAPM + pos;
            disp[off] = 1.f;
            comb[off] = pn * f;
        }
    }
    __syncthreads();
    if (t == 0) {
        float invN = 1.f / 4096.f;
        float invA = 1.f / (4096.f * (float)k);
        float aux = 0.f;
#pragma unroll
        for (int e = 0; e < NE; e++)
            aux += (g_probsum[e] * invN) * ((float)totals[e] * invA);
        out[AUX_OFF] = aux * (float)NE;
    }
}

// ---------------------------------------------------------------------------
extern "C" void kernel_launch(void* const* d_in, const int* in_sizes, int n_in,
                              void* d_out, int out_size) {
    const float* X   = (const float*)d_in[0];
    const float* W1  = (const float*)d_in[1];
    const float* b1  = (const float*)d_in[2];
    const float* W2  = (const float*)d_in[3];
    const float* b2  = (const float*)d_in[4];
    const float* Wi1 = (const float*)d_in[5];
    const float* bi1 = (const float*)d_in[6];
    const float* Wi2 = (const float*)d_in[7];
    const float* bi2 = (const float*)d_in[8];
    const float* Wt1 = (const float*)d_in[9];
    const float* bt1 = (const float*)d_in[10];
    const float* Wt2 = (const float*)d_in[11];
    const float* bt2 = (const float*)d_in[12];
    float* out = (float*)d_out;

    float *H1p = nullptr, *Hip = nullptr;
    cudaGetSymbolAddress((void**)&H1p, g_H1);
    cudaGetSymbolAddress((void**)&Hip, g_Hi);

    // 1) zero everything (output poisoned; dispatch/combine are sparse)
    zero_out_kernel<<<2048, 256>>>(out, (long long)out_size);
    init_small_kernel<<<1, 1024>>>();

    // 2) big GEMMs
    gemm_bias_relu<<<dim3(HD / 64, BSZ / 64), dim3(16, 16)>>>(X, W1, b1, H1p, BSZ, HD, HD);
    gemm_bias_relu<<<dim3(HI2 / 64, BSZ / 64), dim3(16, 16)>>>(X, Wi1, bi1, Hip, BSZ, HI2, HD);

    // 3) importance (writes into out) + column means
    imp_kernel<<<BSZ / 8, 256>>>(Wi2, bi2, out + IMP_OFF);
    colmean_kernel<<<64, 256>>>(X);

    // 4) adaptive_k
    tk_kernel<<<1, 256>>>(Wt1, bt1, Wt2, bt2);

    // 5) router logits -> probs -> top2 (writes router_probs into out)
    router_kernel<<<BSZ / 8, 256>>>(W2, b2, out + RP_OFF);

    // 6) order-preserving scan + scatter + aux loss
    scan_scatter_kernel<<<1, 256>>>(out);
}

// round 2
// speedup vs baseline: 1.0780x; 1.0780x over previous
#include <cuda_runtime.h>
#include <math.h>

// Problem constants
#define BSZ   4096        // B*S tokens
#define HD    1024        // hidden
#define NE    16          // experts
#define CAPM  768         // CAP_MAX
#define HI2   512         // H/2

static const long long D_SZ    = (long long)BSZ * NE * CAPM;       // 50331648
static const long long COMB_OFF= D_SZ;
static const long long RP_OFF  = 2 * D_SZ;                         // 100663296
static const long long AUX_OFF = RP_OFF + (long long)BSZ * NE;     // 100728832
static const long long IMP_OFF = AUX_OFF + 1;                      // 100728833

// Scratch (device globals; no cudaMalloc allowed)
__device__ float g_H1[(size_t)BSZ * HD];     // relu(X@W1+b1)   16MB
__device__ float g_Hi[(size_t)BSZ * HI2];    // relu(X@Wi1+bi1)  8MB
__device__ float g_avg[HD];                  // column sums of X
__device__ float g_impsum;                   // sum of importance
__device__ float g_probsum[NE];              // sum of router probs per expert
__device__ float g_tp[BSZ * 2];              // top-2 probs
__device__ int   g_te[BSZ * 2];              // top-2 expert ids
__device__ int   g_k;                        // adaptive_k in {1,2}

// ---------------------------------------------------------------------------
// packed f32x2 helpers (Blackwell FFMA2 path — ptxas never emits this itself)
__device__ __forceinline__ double pack2(float x) {
    double d;
    asm("mov.b64 %0, {%1, %1};" : "=d"(d) : "f"(x));
    return d;
}
__device__ __forceinline__ void fma2(double& acc, double a, double b) {
    asm("fma.rn.f32x2 %0, %1, %2, %0;" : "+d"(acc) : "d"(a), "d"(b));
}
__device__ __forceinline__ float2 unpack2(double d) {
    float2 r;
    asm("mov.b64 {%0, %1}, %2;" : "=f"(r.x), "=f"(r.y) : "d"(d));
    return r;
}

// ---------------------------------------------------------------------------
// zero the dispatch+combine region (poisoned by harness)
__global__ void zero_out_kernel(float* __restrict__ out, long long n) {
    long long stride = (long long)gridDim.x * blockDim.x;
    long long i = (long long)blockIdx.x * blockDim.x + threadIdx.x;
    long long n4 = n >> 2;
    float4 z = make_float4(0.f, 0.f, 0.f, 0.f);
    for (long long j = i; j < n4; j += stride)
        ((float4*)out)[j] = z;
}

// zero small accumulators
__global__ void init_small_kernel() {
    int t = threadIdx.x;
    if (t < HD) g_avg[t] = 0.f;
    if (t < NE) g_probsum[t] = 0.f;
    if (t == 0) g_impsum = 0.f;
}

// ---------------------------------------------------------------------------
// C[M,N] = relu(A[M,K] @ W[K,N] + bias[N])
// 128x128 block tile, BK=8, 256 threads, 8x8 per thread, inner product in
// packed f32x2 (two fp32 FMAs per instruction).
__global__ __launch_bounds__(256, 2)
void sgemm_relu_f32x2(const float* __restrict__ A, const float* __restrict__ W,
                      const float* __restrict__ bias, float* __restrict__ C,
                      int M, int N, int K) {
    __shared__ float As[8][128];   // transposed A tile
    __shared__ float Bs[8][128];

    const int tid  = threadIdx.x;
    const int m0   = blockIdx.y * 128;
    const int n0   = blockIdx.x * 128;
    const int arow = tid >> 1;            // 0..127
    const int acol = (tid & 1) * 4;       // 0 or 4
    const int brow = tid >> 5;            // 0..7
    const int bcol = (tid & 31) * 4;      // 0..124
    const int trow = (tid >> 4) * 8;      // 0..120
    const int tcol = (tid & 15) * 8;      // 0..120

    double acc[8][4];                      // 8 rows x 4 packed col-pairs
#pragma unroll
    for (int i = 0; i < 8; i++)
#pragma unroll
        for (int j = 0; j < 4; j++) acc[i][j] = 0.0;

    const float* Aptr = A + (size_t)(m0 + arow) * K + acol;
    const float* Wptr = W + (size_t)brow * N + n0 + bcol;

    float4 av = *(const float4*)(Aptr);
    float4 bv = *(const float4*)(Wptr);

    for (int kk = 0; kk < K; kk += 8) {
        As[acol + 0][arow] = av.x;
        As[acol + 1][arow] = av.y;
        As[acol + 2][arow] = av.z;
        As[acol + 3][arow] = av.w;
        *(float4*)&Bs[brow][bcol] = bv;
        __syncthreads();

        if (kk + 8 < K) {                  // prefetch next tiles
            av = *(const float4*)(Aptr + kk + 8);
            bv = *(const float4*)(Wptr + (size_t)(kk + 8) * N);
        }

#pragma unroll
        for (int k = 0; k < 8; k++) {
            float4 a0 = *(const float4*)&As[k][trow];
            float4 a1 = *(const float4*)&As[k][trow + 4];
            double2 b0 = *(const double2*)&Bs[k][tcol];       // (c0,c1),(c2,c3)
            double2 b1 = *(const double2*)&Bs[k][tcol + 4];   // (c4,c5),(c6,c7)
            double ad[8];
            ad[0] = pack2(a0.x); ad[1] = pack2(a0.y);
            ad[2] = pack2(a0.z); ad[3] = pack2(a0.w);
            ad[4] = pack2(a1.x); ad[5] = pack2(a1.y);
            ad[6] = pack2(a1.z); ad[7] = pack2(a1.w);
#pragma unroll
            for (int i = 0; i < 8; i++) {
                fma2(acc[i][0], ad[i], b0.x);
                fma2(acc[i][1], ad[i], b0.y);
                fma2(acc[i][2], ad[i], b1.x);
                fma2(acc[i][3], ad[i], b1.y);
            }
        }
        __syncthreads();
    }

    float4 bias0 = *(const float4*)&bias[n0 + tcol];
    float4 bias1 = *(const float4*)&bias[n0 + tcol + 4];
#pragma unroll
    for (int i = 0; i < 8; i++) {
        int row = m0 + trow + i;
        float2 p0 = unpack2(acc[i][0]);
        float2 p1 = unpack2(acc[i][1]);
        float2 p2 = unpack2(acc[i][2]);
        float2 p3 = unpack2(acc[i][3]);
        float4 o0, o1;
        o0.x = fmaxf(p0.x + bias0.x, 0.f);
        o0.y = fmaxf(p0.y + bias0.y, 0.f);
        o0.z = fmaxf(p1.x + bias0.z, 0.f);
        o0.w = fmaxf(p1.y + bias0.w, 0.f);
        o1.x = fmaxf(p2.x + bias1.x, 0.f);
        o1.y = fmaxf(p2.y + bias1.y, 0.f);
        o1.z = fmaxf(p3.x + bias1.z, 0.f);
        o1.w = fmaxf(p3.y + bias1.w, 0.f);
        *(float4*)(C + (size_t)row * N + n0 + tcol)     = o0;
        *(float4*)(C + (size_t)row * N + n0 + tcol + 4) = o1;
    }
}

// ---------------------------------------------------------------------------
// importance = sigmoid(Hi @ Wi2 + bi2); one warp per token
__global__ __launch_bounds__(256)
void imp_kernel(const float* __restrict__ Wi2, const float* __restrict__ bi2,
                float* __restrict__ out_imp) {
    __shared__ float w[HI2];
    int t = threadIdx.x;
    w[t] = Wi2[t];
    w[t + 256] = Wi2[t + 256];
    __syncthreads();
    int warp = t >> 5, lane = t & 31;
    int token = blockIdx.x * 8 + warp;
    const float* h = g_Hi + (size_t)token * HI2;
    float acc = 0.f;
#pragma unroll
    for (int i = 0; i < HI2 / 32; i++)
        acc += h[lane + 32 * i] * w[lane + 32 * i];
#pragma unroll
    for (int o = 16; o; o >>= 1) acc += __shfl_xor_sync(0xffffffffu, acc, o);
    if (lane == 0) {
        float v = 1.f / (1.f + expf(-(acc + bi2[0])));
        out_imp[token] = v;
        atomicAdd(&g_impsum, v);
    }
}

// column sums of X -> g_avg (divide by 4096 later)
__global__ __launch_bounds__(256)
void colmean_kernel(const float* __restrict__ X) {
    int t = threadIdx.x;
    int r0 = blockIdx.x * 64;
    float4 s = make_float4(0.f, 0.f, 0.f, 0.f);
    for (int r = r0; r < r0 + 64; r++) {
        float4 v = ((const float4*)X)[(size_t)r * 256 + t];
        s.x += v.x; s.y += v.y; s.z += v.z; s.w += v.w;
    }
    atomicAdd(&g_avg[t * 4 + 0], s.x);
    atomicAdd(&g_avg[t * 4 + 1], s.y);
    atomicAdd(&g_avg[t * 4 + 2], s.z);
    atomicAdd(&g_avg[t * 4 + 3], s.w);
}

// tiny top-k predictor net -> g_k
__global__ __launch_bounds__(256)
void tk_kernel(const float* __restrict__ Wt1, const float* __restrict__ bt1,
               const float* __restrict__ Wt2, const float* __restrict__ bt2) {
    int j = threadIdx.x;  // 256 hidden units
    const float invN = 1.f / 4096.f;
    float acc = bt1[j];
    for (int i = 0; i < HD; i++)
        acc += (g_avg[i] * invN) * Wt1[(size_t)i * 256 + j];
    acc += (g_impsum * invN) * Wt1[(size_t)HD * 256 + j];
    float h = fmaxf(acc, 0.f);
    __shared__ float s0[256], s1[256];
    s0[j] = h * Wt2[j * 2 + 0];
    s1[j] = h * Wt2[j * 2 + 1];
    __syncthreads();
    for (int o = 128; o; o >>= 1) {
        if (j < o) { s0[j] += s0[j + o]; s1[j] += s1[j + o]; }
        __syncthreads();
    }
    if (j == 0) {
        float l0 = s0[0] + bt2[0];
        float l1 = s1[0] + bt2[1];
        g_k = (l1 > l0) ? 2 : 1;   // argmax keeps lower index on tie
    }
}

// ---------------------------------------------------------------------------
// router: logits = H1 @ W2 + b2 -> softmax -> probs + top-2. One warp/token.
__global__ __launch_bounds__(256)
void router_kernel(const float* __restrict__ W2, const float* __restrict__ b2,
                   float* __restrict__ out_rp) {
    __shared__ float ps[NE];
    int t = threadIdx.x, warp = t >> 5, lane = t & 31;
    if (t < NE) ps[t] = 0.f;
    __syncthreads();
    int token = blockIdx.x * 8 + warp;
    const float* h = g_H1 + (size_t)token * HD;
    float acc[NE];
#pragma unroll
    for (int e = 0; e < NE; e++) acc[e] = 0.f;
    for (int i = 0; i < HD / 32; i++) {
        int k = lane + 32 * i;
        float hv = h[k];
        const float4* w = (const float4*)(W2 + (size_t)k * NE);
        float4 w0 = __ldg(w + 0), w1 = __ldg(w + 1), w2 = __ldg(w + 2), w3 = __ldg(w + 3);
        acc[0]  += hv * w0.x; acc[1]  += hv * w0.y; acc[2]  += hv * w0.z; acc[3]  += hv * w0.w;
        acc[4]  += hv * w1.x; acc[5]  += hv * w1.y; acc[6]  += hv * w1.z; acc[7]  += hv * w1.w;
        acc[8]  += hv * w2.x; acc[9]  += hv * w2.y; acc[10] += hv * w2.z; acc[11] += hv * w2.w;
        acc[12] += hv * w3.x; acc[13] += hv * w3.y; acc[14] += hv * w3.z; acc[15] += hv * w3.w;
    }
#pragma unroll
    for (int e = 0; e < NE; e++)
#pragma unroll
        for (int o = 16; o; o >>= 1) acc[e] += __shfl_xor_sync(0xffffffffu, acc[e], o);

    if (lane == 0) {
        float p[NE];
        float mx = -1e30f;
#pragma unroll
        for (int e = 0; e < NE; e++) { p[e] = acc[e] + b2[e]; mx = fmaxf(mx, p[e]); }
        float sum = 0.f;
#pragma unroll
        for (int e = 0; e < NE; e++) { p[e] = expf(p[e] - mx); sum += p[e]; }
        float inv = 1.f / sum;
#pragma unroll
        for (int e = 0; e < NE; e++) p[e] *= inv;
#pragma unroll
        for (int e = 0; e < NE; e++) {
            out_rp[(size_t)token * NE + e] = p[e];
            atomicAdd(&ps[e], p[e]);
        }
        // top-1 / top-2 with lowest-index tie-break (jax.lax.top_k stability)
        int e0 = 0;
#pragma unroll
        for (int e = 1; e < NE; e++) if (p[e] > p[e0]) e0 = e;
        int best = -1; float bv = -1.f;
#pragma unroll
        for (int e = 0; e < NE; e++) {
            if (e == e0) continue;
            if (p[e] > bv) { bv = p[e]; best = e; }
        }
        g_tp[token * 2 + 0] = p[e0];
        g_tp[token * 2 + 1] = p[best];
        g_te[token * 2 + 0] = e0;
        g_te[token * 2 + 1] = best;
    }
    __syncthreads();
    if (t < NE) atomicAdd(&g_probsum[t], ps[t]);
}

// ---------------------------------------------------------------------------
// single-block order-preserving per-expert scan + scatter + aux loss
__global__ __launch_bounds__(256)
void scan_scatter_kernel(float* __restrict__ out) {
    __shared__ int sh[256 * NE];
    __shared__ int totals[NE];
    int t = threadIdx.x;
    int k = g_k;
    int cap = 384 * k;   // floor(4096*1.5*k/16)
    int base = t * 32;   // 32 assignments per thread, N = 8192

#pragma unroll
    for (int e = 0; e < NE; e++) sh[t * NE + e] = 0;
    // pass 1: local counts of valid assignments per expert (in order)
    for (int i = 0; i < 32; i++) {
        int n = base + i;
        int slot = n & 1;
        if (slot < k) {
            int e = g_te[n];
            sh[t * NE + e]++;
        }
    }
    __syncthreads();
    // exclusive prefix across threads, one thread per expert
    if (t < NE) {
        int run = 0;
        for (int i = 0; i < 256; i++) {
            int c = sh[i * NE + t];
            sh[i * NE + t] = run;
            run += c;
        }
        totals[t] = run;
    }
    __syncthreads();

    float* disp = out;
    float* comb = out + COMB_OFF;
    const float* imp = out + IMP_OFF;

    // pass 2: replay, compute positions, scatter writes
    for (int i = 0; i < 32; i++) {
        int n = base + i;
        int token = n >> 1;
        int slot = n & 1;
        if (slot >= k) continue;
        int e = g_te[n];
        int pos = sh[t * NE + e]++;
        if (pos < cap) {
            float tp0 = g_tp[token * 2 + 0];
            float tp1 = g_tp[token * 2 + 1];
            float denom = (k == 2) ? (tp0 + tp1 + 1e-8f) : (tp0 + 1e-8f);
            float pn = ((slot == 0) ? tp0 : tp1) / denom;
            float f = 1.f + ((imp[token] > 0.5f) ? 1.f : 0.f);
            long long off = (long long)token * NE * CAPM + (long long)e * CAPM + pos;
            disp[off] = 1.f;
            comb[off] = pn * f;
        }
    }
    __syncthreads();
    if (t == 0) {
        float invN = 1.f / 4096.f;
        float invA = 1.f / (4096.f * (float)k);
        float aux = 0.f;
#pragma unroll
        for (int e = 0; e < NE; e++)
            aux += (g_probsum[e] * invN) * ((float)totals[e] * invA);
        out[AUX_OFF] = aux * (float)NE;
    }
}

// ---------------------------------------------------------------------------
extern "C" void kernel_launch(void* const* d_in, const int* in_sizes, int n_in,
                              void* d_out, int out_size) {
    const float* X   = (const float*)d_in[0];
    const float* W1  = (const float*)d_in[1];
    const float* b1  = (const float*)d_in[2];
    const float* W2  = (const float*)d_in[3];
    const float* b2  = (const float*)d_in[4];
    const float* Wi1 = (const float*)d_in[5];
    const float* bi1 = (const float*)d_in[6];
    const float* Wi2 = (const float*)d_in[7];
    const float* bi2 = (const float*)d_in[8];
    const float* Wt1 = (const float*)d_in[9];
    const float* bt1 = (const float*)d_in[10];
    const float* Wt2 = (const float*)d_in[11];
    const float* bt2 = (const float*)d_in[12];
    float* out = (float*)d_out;

    float *H1p = nullptr, *Hip = nullptr;
    cudaGetSymbolAddress((void**)&H1p, g_H1);
    cudaGetSymbolAddress((void**)&Hip, g_Hi);

    // side stream + events for overlapping the HBM-bound zero-fill with the
    // FMA-bound GEMMs (created once, outside capture)
    static cudaStream_t s1 = nullptr;
    static cudaEvent_t ev0 = nullptr, evA = nullptr, ev1 = nullptr;
    if (!s1) {
        cudaStreamCreateWithFlags(&s1, cudaStreamNonBlocking);
        cudaEventCreateWithFlags(&ev0, cudaEventDisableTiming);
        cudaEventCreateWithFlags(&evA, cudaEventDisableTiming);
        cudaEventCreateWithFlags(&ev1, cudaEventDisableTiming);
    }

    // fork side stream off the main (captured) stream
    cudaEventRecord(ev0, 0);
    cudaStreamWaitEvent(s1, ev0, 0);

    // side stream: small-accumulator init, big zero-fill, column means of X
    init_small_kernel<<<1, 1024, 0, s1>>>();
    cudaEventRecord(evA, s1);                       // init done
    zero_out_kernel<<<2048, 256, 0, s1>>>(out, 2 * D_SZ);
    colmean_kernel<<<64, 256, 0, s1>>>(X);
    cudaEventRecord(ev1, s1);                       // zero + colmean done

    // main stream: GEMMs (f32x2 FFMA2 path)
    sgemm_relu_f32x2<<<dim3(HI2 / 128, BSZ / 128), 256>>>(X, Wi1, bi1, Hip, BSZ, HI2, HD);
    cudaStreamWaitEvent(0, evA, 0);                 // g_impsum zeroed
    imp_kernel<<<BSZ / 8, 256>>>(Wi2, bi2, out + IMP_OFF);
    sgemm_relu_f32x2<<<dim3(HD / 128, BSZ / 128), 256>>>(X, W1, b1, H1p, BSZ, HD, HD);
    router_kernel<<<BSZ / 8, 256>>>(W2, b2, out + RP_OFF);

    // join: zero-fill + colmean must be done before tk/scan
    cudaStreamWaitEvent(0, ev1, 0);
    tk_kernel<<<1, 256>>>(Wt1, bt1, Wt2, bt2);
    scan_scatter_kernel<<<1, 256>>>(out);
}

// round 4
// speedup vs baseline: 2.0757x; 1.9254x over previous
#include <cuda_runtime.h>
#include <cuda_bf16.h>
#include <math.h>
#include <cstdint>

// Problem constants
#define BSZ   4096        // B*S tokens
#define HD    1024        // hidden
#define NE    16          // experts
#define CAPM  768         // CAP_MAX
#define HI2   512         // H/2
#define NT    1536        // combined N (W1 | Wi1)

static const long long D_SZ    = (long long)BSZ * NE * CAPM;       // 50331648
static const long long COMB_OFF= D_SZ;
static const long long RP_OFF  = 2 * D_SZ;                         // 100663296
static const long long AUX_OFF = RP_OFF + (long long)BSZ * NE;     // 100728832
static const long long IMP_OFF = AUX_OFF + 1;                      // 100728833

// Scratch (device globals; no cudaMalloc allowed)
__device__ float g_H1[(size_t)BSZ * HD];     // relu(X@W1+b1)   16MB
__device__ float g_Hi[(size_t)BSZ * HI2];    // relu(X@Wi1+bi1)  8MB
__device__ __nv_bfloat16 g_A0[(size_t)BSZ * HD];   // bf16 hi split of X
__device__ __nv_bfloat16 g_A1[(size_t)BSZ * HD];   // bf16 lo split of X
__device__ __nv_bfloat16 g_B0[(size_t)HD * NT];    // bf16 hi split of [W1|Wi1]
__device__ __nv_bfloat16 g_B1[(size_t)HD * NT];    // bf16 lo split
__device__ float g_avg[HD];                  // column sums of X
__device__ float g_impsum;                   // sum of importance
__device__ float g_probsum[NE];              // sum of router probs per expert
__device__ float g_tkl[2];                   // top-k predictor logits
__device__ float g_tp[BSZ * 2];              // top-2 probs
__device__ int   g_te[BSZ * 2];              // top-2 expert ids

// ===========================================================================
// mma.sync helpers (portable PTX, no sm_103a-gated instructions)
// ===========================================================================
__device__ __forceinline__ uint32_t smem_to_u32(const void* p) {
    uint32_t a;
    asm("{ .reg .u64 t; cvta.to.shared.u64 t, %1; cvt.u32.u64 %0, t; }" : "=r"(a) : "l"(p));
    return a;
}
#define LDSM4(d, a) \
    asm volatile("ldmatrix.sync.aligned.m8n8.x4.shared.b16 {%0,%1,%2,%3}, [%4];" \
        : "=r"((d)[0]), "=r"((d)[1]), "=r"((d)[2]), "=r"((d)[3]) : "r"(a))
#define LDSM4T(d, a) \
    asm volatile("ldmatrix.sync.aligned.m8n8.x4.trans.shared.b16 {%0,%1,%2,%3}, [%4];" \
        : "=r"((d)[0]), "=r"((d)[1]), "=r"((d)[2]), "=r"((d)[3]) : "r"(a))
#define MMA16816(c, a, b0, b1) \
    asm volatile("mma.sync.aligned.m16n8k16.row.col.f32.bf16.bf16.f32 " \
        "{%0,%1,%2,%3}, {%4,%5,%6,%7}, {%8,%9}, {%0,%1,%2,%3};" \
        : "+f"((c)[0]), "+f"((c)[1]), "+f"((c)[2]), "+f"((c)[3]) \
        : "r"((a)[0]), "r"((a)[1]), "r"((a)[2]), "r"((a)[3]), "r"(b0), "r"(b1))

// smem geometry (bytes): padded rows for conflict-free ldmatrix
#define AS_ROWB   80                     // 32 bf16 + pad -> 80B rows
#define BS_ROWB   272                    // 128 bf16 + pad -> 272B rows
#define A_SPLIT_B (128 * AS_ROWB)        // 10240
#define B_SPLIT_B (32 * BS_ROWB)         // 8704
#define B_OFF     (2 * A_SPLIT_B)        // 20480
#define BUF_B     (B_OFF + 2 * B_SPLIT_B)// 37888
#define SMEMT     (2 * BUF_B)            // 75776

// ===========================================================================
// fused HMMA bf16-split GEMM: [H1|Hi] = relu(X @ [W1|Wi1] + [b1|bi1])
// grid (12, 32), 256 threads; block tile 128x128, BK=32, warp tile 64x32.
// 3 products per k-chunk: A0B0 + A0B1 + A1B0 (A1B1 ~ 2^-16, dropped).
// ===========================================================================
__global__ __launch_bounds__(256, 1)
void gemm_mma(const __nv_bfloat16* __restrict__ A0g, const __nv_bfloat16* __restrict__ A1g,
              const __nv_bfloat16* __restrict__ B0g, const __nv_bfloat16* __restrict__ B1g,
              const float* __restrict__ b1, const float* __restrict__ bi1,
              float* __restrict__ H1, float* __restrict__ Hi) {
    extern __shared__ char smem[];
    const uint32_t sb = smem_to_u32(smem);
    const int tid = threadIdx.x, wid = tid >> 5, lane = tid & 31;
    const int m0 = blockIdx.y * 128;
    const int n0 = blockIdx.x * 128;

    // ---- global->smem loader mapping ----
    const int ar = tid >> 1, ac = (tid & 1) * 16;       // A: row 0..127, 16 bf16 chunk
    const int br = tid >> 3, bc = (tid & 7) * 16;       // B: row 0..31,  16 bf16 chunk
    const __nv_bfloat16* A0p = A0g + (size_t)(m0 + ar) * HD + ac;
    const __nv_bfloat16* A1p = A1g + (size_t)(m0 + ar) * HD + ac;
    const __nv_bfloat16* B0p = B0g + (size_t)br * NT + n0 + bc;
    const __nv_bfloat16* B1p = B1g + (size_t)br * NT + n0 + bc;

    char* As = smem + (size_t)ar * AS_ROWB + ac * 2;    // + buf*BUF_B + split*A_SPLIT_B
    char* Bs = smem + B_OFF + (size_t)br * BS_ROWB + bc * 2;

    uint4 ra0[2], ra1[2], rb0[2], rb1[2];
    auto gload = [&](int i) {
        const uint4* p;
        p = (const uint4*)(A0p + i * 32);               ra0[0] = p[0]; ra0[1] = p[1];
        p = (const uint4*)(A1p + i * 32);               ra1[0] = p[0]; ra1[1] = p[1];
        p = (const uint4*)(B0p + (size_t)i * 32 * NT);  rb0[0] = p[0]; rb0[1] = p[1];
        p = (const uint4*)(B1p + (size_t)i * 32 * NT);  rb1[0] = p[0]; rb1[1] = p[1];
    };
    auto sstore = [&](int buf) {
        char* a = As + buf * BUF_B;
        *(uint4*)(a)              = ra0[0]; *(uint4*)(a + 16)              = ra0[1];
        *(uint4*)(a + A_SPLIT_B)  = ra1[0]; *(uint4*)(a + A_SPLIT_B + 16)  = ra1[1];
        char* b = Bs + buf * BUF_B;
        *(uint4*)(b)              = rb0[0]; *(uint4*)(b + 16)              = rb0[1];
        *(uint4*)(b + B_SPLIT_B)  = rb1[0]; *(uint4*)(b + B_SPLIT_B + 16)  = rb1[1];
    };

    // ---- per-warp ldmatrix base addresses ----
    const int wm = wid >> 2, wn = wid & 3;
    const int mbase = wm * 64, nbase = wn * 32;
    const int l8 = lane & 7, lb8 = (lane >> 3) & 1, lhi = lane >> 4;
    // A: row = mbase + ti*16 + l8 + 8*lb8 ; bytecol = kbase*2 + lhi*16
    const uint32_t aAddr = sb + (uint32_t)(mbase + l8 + 8 * lb8) * AS_ROWB + lhi * 16;
    // B: row = kbase + l8 + 8*lb8 ; bytecol = (nbase + nt*16 + lhi*8)*2
    const uint32_t bAddr = sb + B_OFF + (uint32_t)(l8 + 8 * lb8) * BS_ROWB
                         + (uint32_t)(nbase + lhi * 8) * 2;

    float acc[4][4][4];
#pragma unroll
    for (int i = 0; i < 4; i++)
#pragma unroll
        for (int j = 0; j < 4; j++)
#pragma unroll
            for (int c = 0; c < 4; c++) acc[i][j][c] = 0.f;

    gload(0);
    sstore(0);
    __syncthreads();

    for (int it = 0; it < 32; it++) {
        const int buf = it & 1;
        if (it < 31) gload(it + 1);

        const uint32_t aB = aAddr + buf * BUF_B;
        const uint32_t bB = bAddr + buf * BUF_B;
#pragma unroll
        for (int ks = 0; ks < 2; ks++) {
            const uint32_t aK = aB + ks * 32;            // kbase*2
            const uint32_t bK = bB + ks * 16 * BS_ROWB;  // kbase rows
            uint32_t af[4][4], b0f[2][4], b1f[2][4];
            // A0 fragments (4 m16 tiles)
#pragma unroll
            for (int ti = 0; ti < 4; ti++) LDSM4(af[ti], aK + ti * 16 * AS_ROWB);
            // B0 fragments (2 n16 groups)
#pragma unroll
            for (int nt = 0; nt < 2; nt++) LDSM4T(b0f[nt], bK + nt * 32);
#pragma unroll
            for (int ti = 0; ti < 4; ti++)
#pragma unroll
                for (int nj = 0; nj < 4; nj++)
                    MMA16816(acc[ti][nj], af[ti], b0f[nj >> 1][(nj & 1) * 2], b0f[nj >> 1][(nj & 1) * 2 + 1]);
            // B1 fragments, reuse A0
#pragma unroll
            for (int nt = 0; nt < 2; nt++) LDSM4T(b1f[nt], bK + B_SPLIT_B + nt * 32);
#pragma unroll
            for (int ti = 0; ti < 4; ti++)
#pragma unroll
                for (int nj = 0; nj < 4; nj++)
                    MMA16816(acc[ti][nj], af[ti], b1f[nj >> 1][(nj & 1) * 2], b1f[nj >> 1][(nj & 1) * 2 + 1]);
            // A1 fragments (overwrite af), reuse B0
#pragma unroll
            for (int ti = 0; ti < 4; ti++) LDSM4(af[ti], aK + A_SPLIT_B + ti * 16 * AS_ROWB);
#pragma unroll
            for (int ti = 0; ti < 4; ti++)
#pragma unroll
                for (int nj = 0; nj < 4; nj++)
                    MMA16816(acc[ti][nj], af[ti], b0f[nj >> 1][(nj & 1) * 2], b0f[nj >> 1][(nj & 1) * 2 + 1]);
        }
        __syncthreads();
        if (it < 31) {
            sstore(buf ^ 1);
            __syncthreads();
        }
    }

    // ---- epilogue: bias + relu, direct global stores ----
    const bool isH1 = (n0 < HD);
    float* dst = isH1 ? H1 : Hi;
    const int stride = isH1 ? HD : HI2;
    const int nadj = isH1 ? n0 : (n0 - HD);
    const float* bias = isH1 ? b1 : bi1;
#pragma unroll
    for (int ti = 0; ti < 4; ti++) {
        const int r0 = m0 + mbase + ti * 16 + (lane >> 2);
#pragma unroll
        for (int nj = 0; nj < 4; nj++) {
            const int cn = nadj + nbase + nj * 8 + (lane & 3) * 2;
            const float bx = __ldg(bias + cn), by = __ldg(bias + cn + 1);
            float2 v0, v1;
            v0.x = fmaxf(acc[ti][nj][0] + bx, 0.f);
            v0.y = fmaxf(acc[ti][nj][1] + by, 0.f);
            v1.x = fmaxf(acc[ti][nj][2] + bx, 0.f);
            v1.y = fmaxf(acc[ti][nj][3] + by, 0.f);
            *(float2*)(dst + (size_t)r0 * stride + cn)       = v0;
            *(float2*)(dst + (size_t)(r0 + 8) * stride + cn) = v1;
        }
    }
}

// ===========================================================================
// pre-pass converters: fp32 -> bf16 split pair
// ===========================================================================
__device__ __forceinline__ void split_bf16(float f, __nv_bfloat16& h0, __nv_bfloat16& h1) {
    h0 = __float2bfloat16_rn(f);
    h1 = __float2bfloat16_rn(f - __bfloat162float(h0));
}

__global__ __launch_bounds__(256)
void convA_kernel(const float* __restrict__ X) {
    size_t i = (size_t)blockIdx.x * 256 + threadIdx.x;   // over 1M float4
    float4 v = ((const float4*)X)[i];
    __nv_bfloat162 a0, a1, b0, b1;
    split_bf16(v.x, a0.x, a1.x); split_bf16(v.y, a0.y, a1.y);
    split_bf16(v.z, b0.x, b1.x); split_bf16(v.w, b0.y, b1.y);
    ((__nv_bfloat162*)g_A0)[2 * i]     = a0;
    ((__nv_bfloat162*)g_A0)[2 * i + 1] = b0;
    ((__nv_bfloat162*)g_A1)[2 * i]     = a1;
    ((__nv_bfloat162*)g_A1)[2 * i + 1] = b1;
}

__global__ __launch_bounds__(256)
void convB_kernel(const float* __restrict__ W1, const float* __restrict__ Wi1) {
    size_t i = (size_t)blockIdx.x * 256 + threadIdx.x;   // over 1024*1536/4 float4
    int r = (int)(i / 384);
    int c = (int)(i % 384) * 4;
    float4 v = (c < HD) ? *(const float4*)(W1 + (size_t)r * HD + c)
                        : *(const float4*)(Wi1 + (size_t)r * HI2 + c - HD);
    __nv_bfloat162 a0, a1, b0, b1;
    split_bf16(v.x, a0.x, a1.x); split_bf16(v.y, a0.y, a1.y);
    split_bf16(v.z, b0.x, b1.x); split_bf16(v.w, b0.y, b1.y);
    ((__nv_bfloat162*)g_B0)[2 * i]     = a0;
    ((__nv_bfloat162*)g_B0)[2 * i + 1] = b0;
    ((__nv_bfloat162*)g_B1)[2 * i]     = a1;
    ((__nv_bfloat162*)g_B1)[2 * i + 1] = b1;
}

// ===========================================================================
// zero dispatch+combine region (poisoned by harness)
__global__ void zero_out_kernel(float* __restrict__ out, long long n) {
    long long stride = (long long)gridDim.x * blockDim.x;
    long long i = (long long)blockIdx.x * blockDim.x + threadIdx.x;
    long long n4 = n >> 2;
    float4 z = make_float4(0.f, 0.f, 0.f, 0.f);
    for (long long j = i; j < n4; j += stride)
        ((float4*)out)[j] = z;
}

__global__ void init_small_kernel() {
    int t = threadIdx.x;
    if (t < HD) g_avg[t] = 0.f;
    if (t < NE) g_probsum[t] = 0.f;
    if (t == 0) g_impsum = 0.f;
    if (t < 2) g_tkl[t] = 0.f;
}

// ---------------------------------------------------------------------------
// importance = sigmoid(Hi @ Wi2 + bi2); one warp per token
__global__ __launch_bounds__(256)
void imp_kernel(const float* __restrict__ Wi2, const float* __restrict__ bi2,
                float* __restrict__ out_imp) {
    __shared__ float w[HI2];
    int t = threadIdx.x;
    w[t] = Wi2[t];
    w[t + 256] = Wi2[t + 256];
    __syncthreads();
    int warp = t >> 5, lane = t & 31;
    int token = blockIdx.x * 8 + warp;
    const float* h = g_Hi + (size_t)token * HI2;
    float acc = 0.f;
#pragma unroll
    for (int i = 0; i < HI2 / 32; i++)
        acc += h[lane + 32 * i] * w[lane + 32 * i];
#pragma unroll
    for (int o = 16; o; o >>= 1) acc += __shfl_xor_sync(0xffffffffu, acc, o);
    if (lane == 0) {
        float v = 1.f / (1.f + expf(-(acc + bi2[0])));
        out_imp[token] = v;
        atomicAdd(&g_impsum, v);
    }
}

// column sums of X -> g_avg
__global__ __launch_bounds__(256)
void colmean_kernel(const float* __restrict__ X) {
    int t = threadIdx.x;
    int r0 = blockIdx.x * 64;
    float4 s = make_float4(0.f, 0.f, 0.f, 0.f);
    for (int r = r0; r < r0 + 64; r++) {
        float4 v = ((const float4*)X)[(size_t)r * 256 + t];
        s.x += v.x; s.y += v.y; s.z += v.z; s.w += v.w;
    }
    atomicAdd(&g_avg[t * 4 + 0], s.x);
    atomicAdd(&g_avg[t * 4 + 1], s.y);
    atomicAdd(&g_avg[t * 4 + 2], s.z);
    atomicAdd(&g_avg[t * 4 + 3], s.w);
}

// top-k predictor matvec: block j computes hidden unit j, accumulates logits
__global__ __launch_bounds__(256)
void tk_matvec_kernel(const float* __restrict__ Wt1, const float* __restrict__ bt1,
                      const float* __restrict__ Wt2, const float* __restrict__ bt2) {
    int j = blockIdx.x, t = threadIdx.x;
    const float invN = 1.f / 4096.f;
    float acc = 0.f;
    for (int i = t; i < HD; i += 256)
        acc += (g_avg[i] * invN) * Wt1[(size_t)i * 256 + j];
    __shared__ float s[256];
    s[t] = acc;
    __syncthreads();
    for (int o = 128; o; o >>= 1) {
        if (t < o) s[t] += s[t + o];
        __syncthreads();
    }
    if (t == 0) {
        float a = s[0] + (g_impsum * invN) * Wt1[(size_t)HD * 256 + j] + bt1[j];
        float h = fmaxf(a, 0.f);
        atomicAdd(&g_tkl[0], h * Wt2[j * 2 + 0]);
        atomicAdd(&g_tkl[1], h * Wt2[j * 2 + 1]);
        if (j == 0) {
            atomicAdd(&g_tkl[0], bt2[0]);
            atomicAdd(&g_tkl[1], bt2[1]);
        }
    }
}

// ---------------------------------------------------------------------------
// router: logits = H1 @ W2 + b2 -> softmax -> probs + top-2. One warp/token.
__global__ __launch_bounds__(256)
void router_kernel(const float* __restrict__ W2, const float* __restrict__ b2,
                   float* __restrict__ out_rp) {
    __shared__ float ps[NE];
    int t = threadIdx.x, warp = t >> 5, lane = t & 31;
    if (t < NE) ps[t] = 0.f;
    __syncthreads();
    int token = blockIdx.x * 8 + warp;
    const float* h = g_H1 + (size_t)token * HD;
    float acc[NE];
#pragma unroll
    for (int e = 0; e < NE; e++) acc[e] = 0.f;
    for (int i = 0; i < HD / 32; i++) {
        int k = lane + 32 * i;
        float hv = h[k];
        const float4* w = (const float4*)(W2 + (size_t)k * NE);
        float4 w0 = __ldg(w + 0), w1 = __ldg(w + 1), w2 = __ldg(w + 2), w3 = __ldg(w + 3);
        acc[0]  += hv * w0.x; acc[1]  += hv * w0.y; acc[2]  += hv * w0.z; acc[3]  += hv * w0.w;
        acc[4]  += hv * w1.x; acc[5]  += hv * w1.y; acc[6]  += hv * w1.z; acc[7]  += hv * w1.w;
        acc[8]  += hv * w2.x; acc[9]  += hv * w2.y; acc[10] += hv * w2.z; acc[11] += hv * w2.w;
        acc[12] += hv * w3.x; acc[13] += hv * w3.y; acc[14] += hv * w3.z; acc[15] += hv * w3.w;
    }
#pragma unroll
    for (int e = 0; e < NE; e++)
#pragma unroll
        for (int o = 16; o; o >>= 1) acc[e] += __shfl_xor_sync(0xffffffffu, acc[e], o);

    if (lane == 0) {
        float p[NE];
        float mx = -1e30f;
#pragma unroll
        for (int e = 0; e < NE; e++) { p[e] = acc[e] + b2[e]; mx = fmaxf(mx, p[e]); }
        float sum = 0.f;
#pragma unroll
        for (int e = 0; e < NE; e++) { p[e] = expf(p[e] - mx); sum += p[e]; }
        float inv = 1.f / sum;
#pragma unroll
        for (int e = 0; e < NE; e++) p[e] *= inv;
#pragma unroll
        for (int e = 0; e < NE; e++) {
            out_rp[(size_t)token * NE + e] = p[e];
            atomicAdd(&ps[e], p[e]);
        }
        int e0 = 0;
#pragma unroll
        for (int e = 1; e < NE; e++) if (p[e] > p[e0]) e0 = e;
        int best = -1; float bv = -1.f;
#pragma unroll
        for (int e = 0; e < NE; e++) {
            if (e == e0) continue;
            if (p[e] > bv) { bv = p[e]; best = e; }
        }
        g_tp[token * 2 + 0] = p[e0];
        g_tp[token * 2 + 1] = p[best];
        g_te[token * 2 + 0] = e0;
        g_te[token * 2 + 1] = best;
    }
    __syncthreads();
    if (t < NE) atomicAdd(&g_probsum[t], ps[t]);
}

// ---------------------------------------------------------------------------
// single-block order-preserving per-expert scan + scatter + aux loss
__global__ __launch_bounds__(256)
void scan_scatter_kernel(float* __restrict__ out) {
    __shared__ int sh[256 * NE];
    __shared__ int totals[NE];
    int t = threadIdx.x;
    int k = (g_tkl[1] > g_tkl[0]) ? 2 : 1;
    int cap = 384 * k;
    int base = t * 32;

#pragma unroll
    for (int e = 0; e < NE; e++) sh[t * NE + e] = 0;
    for (int i = 0; i < 32; i++) {
        int n = base + i;
        int slot = n & 1;
        if (slot < k) sh[t * NE + g_te[n]]++;
    }
    __syncthreads();
    if (t < NE) {
        int run = 0;
        for (int i = 0; i < 256; i++) {
            int c = sh[i * NE + t];
            sh[i * NE + t] = run;
            run += c;
        }
        totals[t] = run;
    }
    __syncthreads();

    float* disp = out;
    float* comb = out + COMB_OFF;
    const float* imp = out + IMP_OFF;

    for (int i = 0; i < 32; i++) {
        int n = base + i;
        int token = n >> 1;
        int slot = n & 1;
        if (slot >= k) continue;
        int e = g_te[n];
        int pos = sh[t * NE + e]++;
        if (pos < cap) {
            float tp0 = g_tp[token * 2 + 0];
            float tp1 = g_tp[token * 2 + 1];
            float denom = (k == 2) ? (tp0 + tp1 + 1e-8f) : (tp0 + 1e-8f);
            float pn = ((slot == 0) ? tp0 : tp1) / denom;
            float f = 1.f + ((imp[token] > 0.5f) ? 1.f : 0.f);
            long long off = (long long)token * NE * CAPM + (long long)e * CAPM + pos;
            disp[off] = 1.f;
            comb[off] = pn * f;
        }
    }
    __syncthreads();
    if (t == 0) {
        float invN = 1.f / 4096.f;
        float invA = 1.f / (4096.f * (float)k);
        float aux = 0.f;
#pragma unroll
        for (int e = 0; e < NE; e++)
            aux += (g_probsum[e] * invN) * ((float)totals[e] * invA);
        out[AUX_OFF] = aux * (float)NE;
    }
}

// ---------------------------------------------------------------------------
extern "C" void kernel_launch(void* const* d_in, const int* in_sizes, int n_in,
                              void* d_out, int out_size) {
    const float* X   = (const float*)d_in[0];
    const float* W1  = (const float*)d_in[1];
    const float* b1  = (const float*)d_in[2];
    const float* W2  = (const float*)d_in[3];
    const float* b2  = (const float*)d_in[4];
    const float* Wi1 = (const float*)d_in[5];
    const float* bi1 = (const float*)d_in[6];
    const float* Wi2 = (const float*)d_in[7];
    const float* bi2 = (const float*)d_in[8];
    const float* Wt1 = (const float*)d_in[9];
    const float* bt1 = (const float*)d_in[10];
    const float* Wt2 = (const float*)d_in[11];
    const float* bt2 = (const float*)d_in[12];
    float* out = (float*)d_out;

    float *H1p = nullptr, *Hip = nullptr;
    __nv_bfloat16 *A0p = nullptr, *A1p = nullptr, *B0p = nullptr, *B1p = nullptr;
    cudaGetSymbolAddress((void**)&H1p, g_H1);
    cudaGetSymbolAddress((void**)&Hip, g_Hi);
    cudaGetSymbolAddress((void**)&A0p, g_A0);
    cudaGetSymbolAddress((void**)&A1p, g_A1);
    cudaGetSymbolAddress((void**)&B0p, g_B0);
    cudaGetSymbolAddress((void**)&B1p, g_B1);

    cudaFuncSetAttribute(gemm_mma, cudaFuncAttributeMaxDynamicSharedMemorySize, SMEMT);

    static cudaStream_t s1 = nullptr;
    static cudaEvent_t ev0 = nullptr, evA = nullptr, ev1 = nullptr;
    if (!s1) {
        cudaStreamCreateWithFlags(&s1, cudaStreamNonBlocking);
        cudaEventCreateWithFlags(&ev0, cudaEventDisableTiming);
        cudaEventCreateWithFlags(&evA, cudaEventDisableTiming);
        cudaEventCreateWithFlags(&ev1, cudaEventDisableTiming);
    }

    // fork side stream
    cudaEventRecord(ev0, 0);
    cudaStreamWaitEvent(s1, ev0, 0);

    // side stream: init accumulators, big zero-fill, column means
    init_small_kernel<<<1, 1024, 0, s1>>>();
    cudaEventRecord(evA, s1);
    zero_out_kernel<<<2048, 256, 0, s1>>>(out, 2 * D_SZ);
    colmean_kernel<<<64, 256, 0, s1>>>(X);
    cudaEventRecord(ev1, s1);

    // main: split-convert operands, HMMA tensor-core GEMM (both GEMMs fused)
    convA_kernel<<<4096, 256>>>(X);
    convB_kernel<<<1536, 256>>>(W1, Wi1);
    gemm_mma<<<dim3(NT / 128, BSZ / 128), 256, SMEMT>>>(A0p, A1p, B0p, B1p, b1, bi1, H1p, Hip);

    cudaStreamWaitEvent(0, evA, 0);                 // accumulators zeroed
    imp_kernel<<<BSZ / 8, 256>>>(Wi2, bi2, out + IMP_OFF);
    router_kernel<<<BSZ / 8, 256>>>(W2, b2, out + RP_OFF);

    cudaStreamWaitEvent(0, ev1, 0);                 // colmean + zero-fill done
    tk_matvec_kernel<<<256, 256>>>(Wt1, bt1, Wt2, bt2);
    scan_scatter_kernel<<<1, 256>>>(out);
}

// round 5
// speedup vs baseline: 2.1650x; 1.0430x over previous
#include <cuda_runtime.h>
#include <cuda_bf16.h>
#include <math.h>
#include <cstdint>

// Problem constants
#define BSZ   4096        // B*S tokens
#define HD    1024        // hidden
#define NE    16          // experts
#define CAPM  768         // CAP_MAX
#define HI2   512         // H/2
#define NT    1536        // combined N (W1 | Wi1)

static const long long D_SZ    = (long long)BSZ * NE * CAPM;       // 50331648
static const long long COMB_OFF= D_SZ;
static const long long RP_OFF  = 2 * D_SZ;                         // 100663296
static const long long AUX_OFF = RP_OFF + (long long)BSZ * NE;     // 100728832
static const long long IMP_OFF = AUX_OFF + 1;                      // 100728833

// Scratch (device globals; no cudaMalloc allowed)
__device__ float g_H1[(size_t)BSZ * HD];     // relu(X@W1+b1)   16MB
__device__ float g_Hi[(size_t)BSZ * HI2];    // relu(X@Wi1+bi1)  8MB
__device__ __nv_bfloat16 g_A0[(size_t)BSZ * HD];   // bf16 hi split of X
__device__ __nv_bfloat16 g_A1[(size_t)BSZ * HD];   // bf16 lo split of X
__device__ __nv_bfloat16 g_B0[(size_t)HD * NT];    // bf16 hi split of [W1|Wi1]
__device__ __nv_bfloat16 g_B1[(size_t)HD * NT];    // bf16 lo split
__device__ float g_avg[HD];                  // column sums of X
__device__ float g_impsum;                   // sum of importance
__device__ float g_probsum[NE];              // sum of router probs per expert
__device__ float g_tkl[2];                   // top-k predictor logits
__device__ float g_aux;                      // aux loss accumulator
__device__ float g_tp[BSZ * 2];              // top-2 probs
__device__ int   g_te[BSZ * 2];              // top-2 expert ids

// ===========================================================================
// PTX helpers (portable; nothing sm_103a-suffix-gated)
// ===========================================================================
__device__ __forceinline__ uint32_t smem_to_u32(const void* p) {
    uint32_t a;
    asm("{ .reg .u64 t; cvta.to.shared.u64 t, %1; cvt.u32.u64 %0, t; }" : "=r"(a) : "l"(p));
    return a;
}
#define LDSM4(d, a) \
    asm volatile("ldmatrix.sync.aligned.m8n8.x4.shared.b16 {%0,%1,%2,%3}, [%4];" \
        : "=r"((d)[0]), "=r"((d)[1]), "=r"((d)[2]), "=r"((d)[3]) : "r"(a))
#define LDSM4T(d, a) \
    asm volatile("ldmatrix.sync.aligned.m8n8.x4.trans.shared.b16 {%0,%1,%2,%3}, [%4];" \
        : "=r"((d)[0]), "=r"((d)[1]), "=r"((d)[2]), "=r"((d)[3]) : "r"(a))
#define MMA16816(c, a, b0, b1) \
    asm volatile("mma.sync.aligned.m16n8k16.row.col.f32.bf16.bf16.f32 " \
        "{%0,%1,%2,%3}, {%4,%5,%6,%7}, {%8,%9}, {%0,%1,%2,%3};" \
        : "+f"((c)[0]), "+f"((c)[1]), "+f"((c)[2]), "+f"((c)[3]) \
        : "r"((a)[0]), "r"((a)[1]), "r"((a)[2]), "r"((a)[3]), "r"(b0), "r"(b1))
#define CP16(s, g) \
    asm volatile("cp.async.cg.shared.global [%0], [%1], 16;" :: "r"(s), "l"(g))
#define CP_COMMIT() asm volatile("cp.async.commit_group;" ::: "memory")
#define CP_WAIT1()  asm volatile("cp.async.wait_group 1;" ::: "memory")
#define CP_WAIT0()  asm volatile("cp.async.wait_group 0;" ::: "memory")

// smem geometry (bytes): padded rows for conflict-free ldmatrix
#define AS_ROWB   80                     // 32 bf16 + pad -> 80B rows
#define BS_ROWB   272                    // 128 bf16 + pad -> 272B rows
#define A_SPLIT_B (128 * AS_ROWB)        // 10240
#define B_SPLIT_B (32 * BS_ROWB)         // 8704
#define B_OFF     (2 * A_SPLIT_B)        // 20480
#define BUF_B     (B_OFF + 2 * B_SPLIT_B)// 37888
#define SMEMT     (2 * BUF_B)            // 75776

// ===========================================================================
// fused HMMA bf16-split GEMM: [H1|Hi] = relu(X @ [W1|Wi1] + [b1|bi1])
// grid (12, 32), 256 threads; block tile 128x128, BK=32, warp tile 64x32.
// cp.async double-buffered; 2 CTAs/SM. 3 products: A0B0 + A0B1 + A1B0.
// ===========================================================================
__global__ __launch_bounds__(256, 2)
void gemm_mma(const __nv_bfloat16* __restrict__ A0g, const __nv_bfloat16* __restrict__ A1g,
              const __nv_bfloat16* __restrict__ B0g, const __nv_bfloat16* __restrict__ B1g,
              const float* __restrict__ b1, const float* __restrict__ bi1,
              float* __restrict__ H1, float* __restrict__ Hi) {
    extern __shared__ char smem[];
    const uint32_t sb = smem_to_u32(smem);
    const int tid = threadIdx.x, wid = tid >> 5, lane = tid & 31;
    const int m0 = blockIdx.y * 128;
    const int n0 = blockIdx.x * 128;

    // ---- global->smem loader mapping (cp.async, 8 x 16B per thread/buf) ----
    const int ar = tid >> 1, ac = (tid & 1) * 16;       // A: row 0..127, 16 bf16 chunk
    const int br = tid >> 3, bc = (tid & 7) * 16;       // B: row 0..31,  16 bf16 chunk
    const __nv_bfloat16* A0p = A0g + (size_t)(m0 + ar) * HD + ac;
    const __nv_bfloat16* A1p = A1g + (size_t)(m0 + ar) * HD + ac;
    const __nv_bfloat16* B0p = B0g + (size_t)br * NT + n0 + bc;
    const __nv_bfloat16* B1p = B1g + (size_t)br * NT + n0 + bc;
    const uint32_t asw = sb + (uint32_t)ar * AS_ROWB + ac * 2;
    const uint32_t bsw = sb + B_OFF + (uint32_t)br * BS_ROWB + bc * 2;

    auto issue = [&](int it, int buf) {
        const uint32_t a = asw + buf * BUF_B;
        const __nv_bfloat16* pa0 = A0p + it * 32;
        const __nv_bfloat16* pa1 = A1p + it * 32;
        CP16(a,                  pa0);
        CP16(a + 16,             pa0 + 8);
        CP16(a + A_SPLIT_B,      pa1);
        CP16(a + A_SPLIT_B + 16, pa1 + 8);
        const uint32_t b = bsw + buf * BUF_B;
        const __nv_bfloat16* pb0 = B0p + (size_t)it * 32 * NT;
        const __nv_bfloat16* pb1 = B1p + (size_t)it * 32 * NT;
        CP16(b,                  pb0);
        CP16(b + 16,             pb0 + 8);
        CP16(b + B_SPLIT_B,      pb1);
        CP16(b + B_SPLIT_B + 16, pb1 + 8);
        CP_COMMIT();
    };

    // ---- per-warp ldmatrix base addresses ----
    const int wm = wid >> 2, wn = wid & 3;
    const int mbase = wm * 64, nbase = wn * 32;
    const int l8 = lane & 7, lb8 = (lane >> 3) & 1, lhi = lane >> 4;
    const uint32_t aAddr = sb + (uint32_t)(mbase + l8 + 8 * lb8) * AS_ROWB + lhi * 16;
    const uint32_t bAddr = sb + B_OFF + (uint32_t)(l8 + 8 * lb8) * BS_ROWB
                         + (uint32_t)(nbase + lhi * 8) * 2;

    float acc[4][4][4];
#pragma unroll
    for (int i = 0; i < 4; i++)
#pragma unroll
        for (int j = 0; j < 4; j++)
#pragma unroll
            for (int c = 0; c < 4; c++) acc[i][j][c] = 0.f;

    issue(0, 0);

    for (int it = 0; it < 32; it++) {
        const int buf = it & 1;
        if (it < 31) { issue(it + 1, buf ^ 1); CP_WAIT1(); }
        else         { CP_WAIT0(); }
        __syncthreads();

        const uint32_t aB = aAddr + buf * BUF_B;
        const uint32_t bB = bAddr + buf * BUF_B;
#pragma unroll
        for (int ks = 0; ks < 2; ks++) {
            const uint32_t aK = aB + ks * 32;            // kbase*2 bytes
            const uint32_t bK = bB + ks * 16 * BS_ROWB;  // kbase rows
            uint32_t af[4][4], b0f[2][4], b1f[2][4];
#pragma unroll
            for (int ti = 0; ti < 4; ti++) LDSM4(af[ti], aK + ti * 16 * AS_ROWB);
#pragma unroll
            for (int nt = 0; nt < 2; nt++) LDSM4T(b0f[nt], bK + nt * 32);
#pragma unroll
            for (int ti = 0; ti < 4; ti++)
#pragma unroll
                for (int nj = 0; nj < 4; nj++)
                    MMA16816(acc[ti][nj], af[ti], b0f[nj >> 1][(nj & 1) * 2], b0f[nj >> 1][(nj & 1) * 2 + 1]);
#pragma unroll
            for (int nt = 0; nt < 2; nt++) LDSM4T(b1f[nt], bK + B_SPLIT_B + nt * 32);
#pragma unroll
            for (int ti = 0; ti < 4; ti++)
#pragma unroll
                for (int nj = 0; nj < 4; nj++)
                    MMA16816(acc[ti][nj], af[ti], b1f[nj >> 1][(nj & 1) * 2], b1f[nj >> 1][(nj & 1) * 2 + 1]);
#pragma unroll
            for (int ti = 0; ti < 4; ti++) LDSM4(af[ti], aK + A_SPLIT_B + ti * 16 * AS_ROWB);
#pragma unroll
            for (int ti = 0; ti < 4; ti++)
#pragma unroll
                for (int nj = 0; nj < 4; nj++)
                    MMA16816(acc[ti][nj], af[ti], b0f[nj >> 1][(nj & 1) * 2], b0f[nj >> 1][(nj & 1) * 2 + 1]);
        }
        __syncthreads();
    }

    // ---- epilogue: bias + relu, direct global stores ----
    const bool isH1 = (n0 < HD);
    float* dst = isH1 ? H1 : Hi;
    const int stride = isH1 ? HD : HI2;
    const int nadj = isH1 ? n0 : (n0 - HD);
    const float* bias = isH1 ? b1 : bi1;
#pragma unroll
    for (int ti = 0; ti < 4; ti++) {
        const int r0 = m0 + mbase + ti * 16 + (lane >> 2);
#pragma unroll
        for (int nj = 0; nj < 4; nj++) {
            const int cn = nadj + nbase + nj * 8 + (lane & 3) * 2;
            const float bx = __ldg(bias + cn), by = __ldg(bias + cn + 1);
            float2 v0, v1;
            v0.x = fmaxf(acc[ti][nj][0] + bx, 0.f);
            v0.y = fmaxf(acc[ti][nj][1] + by, 0.f);
            v1.x = fmaxf(acc[ti][nj][2] + bx, 0.f);
            v1.y = fmaxf(acc[ti][nj][3] + by, 0.f);
            *(float2*)(dst + (size_t)r0 * stride + cn)       = v0;
            *(float2*)(dst + (size_t)(r0 + 8) * stride + cn) = v1;
        }
    }
}

// ===========================================================================
// pre-pass converters: fp32 -> bf16 split pair
// ===========================================================================
__device__ __forceinline__ void split_bf16(float f, __nv_bfloat16& h0, __nv_bfloat16& h1) {
    h0 = __float2bfloat16_rn(f);
    h1 = __float2bfloat16_rn(f - __bfloat162float(h0));
}

__global__ __launch_bounds__(256)
void convA_kernel(const float* __restrict__ X) {
    size_t i = (size_t)blockIdx.x * 256 + threadIdx.x;   // over 1M float4
    float4 v = ((const float4*)X)[i];
    __nv_bfloat162 a0, a1, b0, b1;
    split_bf16(v.x, a0.x, a1.x); split_bf16(v.y, a0.y, a1.y);
    split_bf16(v.z, b0.x, b1.x); split_bf16(v.w, b0.y, b1.y);
    ((__nv_bfloat162*)g_A0)[2 * i]     = a0;
    ((__nv_bfloat162*)g_A0)[2 * i + 1] = b0;
    ((__nv_bfloat162*)g_A1)[2 * i]     = a1;
    ((__nv_bfloat162*)g_A1)[2 * i + 1] = b1;
}

__global__ __launch_bounds__(256)
void convB_kernel(const float* __restrict__ W1, const float* __restrict__ Wi1) {
    size_t i = (size_t)blockIdx.x * 256 + threadIdx.x;   // over 1024*1536/4 float4
    int r = (int)(i / 384);
    int c = (int)(i % 384) * 4;
    float4 v = (c < HD) ? *(const float4*)(W1 + (size_t)r * HD + c)
                        : *(const float4*)(Wi1 + (size_t)r * HI2 + c - HD);
    __nv_bfloat162 a0, a1, b0, b1;
    split_bf16(v.x, a0.x, a1.x); split_bf16(v.y, a0.y, a1.y);
    split_bf16(v.z, b0.x, b1.x); split_bf16(v.w, b0.y, b1.y);
    ((__nv_bfloat162*)g_B0)[2 * i]     = a0;
    ((__nv_bfloat162*)g_B0)[2 * i + 1] = b0;
    ((__nv_bfloat162*)g_B1)[2 * i]     = a1;
    ((__nv_bfloat162*)g_B1)[2 * i + 1] = b1;
}

// ===========================================================================
__global__ void zero_out_kernel(float* __restrict__ out, long long n) {
    long long stride = (long long)gridDim.x * blockDim.x;
    long long i = (long long)blockIdx.x * blockDim.x + threadIdx.x;
    long long n4 = n >> 2;
    float4 z = make_float4(0.f, 0.f, 0.f, 0.f);
    for (long long j = i; j < n4; j += stride)
        ((float4*)out)[j] = z;
}

__global__ void init_small_kernel() {
    int t = threadIdx.x;
    if (t < HD) g_avg[t] = 0.f;
    if (t < NE) g_probsum[t] = 0.f;
    if (t == 0) { g_impsum = 0.f; g_aux = 0.f; }
    if (t < 2) g_tkl[t] = 0.f;
}

// ---------------------------------------------------------------------------
// importance = sigmoid(Hi @ Wi2 + bi2); one warp per token
__global__ __launch_bounds__(256)
void imp_kernel(const float* __restrict__ Wi2, const float* __restrict__ bi2,
                float* __restrict__ out_imp) {
    __shared__ float w[HI2];
    int t = threadIdx.x;
    w[t] = Wi2[t];
    w[t + 256] = Wi2[t + 256];
    __syncthreads();
    int warp = t >> 5, lane = t & 31;
    int token = blockIdx.x * 8 + warp;
    const float* h = g_Hi + (size_t)token * HI2;
    float acc = 0.f;
#pragma unroll
    for (int i = 0; i < HI2 / 32; i++)
        acc += h[lane + 32 * i] * w[lane + 32 * i];
#pragma unroll
    for (int o = 16; o; o >>= 1) acc += __shfl_xor_sync(0xffffffffu, acc, o);
    if (lane == 0) {
        float v = 1.f / (1.f + expf(-(acc + bi2[0])));
        out_imp[token] = v;
        atomicAdd(&g_impsum, v);
    }
}

// column sums of X -> g_avg
__global__ __launch_bounds__(256)
void colmean_kernel(const float* __restrict__ X) {
    int t = threadIdx.x;
    int r0 = blockIdx.x * 64;
    float4 s = make_float4(0.f, 0.f, 0.f, 0.f);
    for (int r = r0; r < r0 + 64; r++) {
        float4 v = ((const float4*)X)[(size_t)r * 256 + t];
        s.x += v.x; s.y += v.y; s.z += v.z; s.w += v.w;
    }
    atomicAdd(&g_avg[t * 4 + 0], s.x);
    atomicAdd(&g_avg[t * 4 + 1], s.y);
    atomicAdd(&g_avg[t * 4 + 2], s.z);
    atomicAdd(&g_avg[t * 4 + 3], s.w);
}

// top-k predictor matvec: block j computes hidden unit j, accumulates logits
__global__ __launch_bounds__(256)
void tk_matvec_kernel(const float* __restrict__ Wt1, const float* __restrict__ bt1,
                      const float* __restrict__ Wt2, const float* __restrict__ bt2) {
    int j = blockIdx.x, t = threadIdx.x;
    const float invN = 1.f / 4096.f;
    float acc = 0.f;
    for (int i = t; i < HD; i += 256)
        acc += (g_avg[i] * invN) * Wt1[(size_t)i * 256 + j];
    __shared__ float s[256];
    s[t] = acc;
    __syncthreads();
    for (int o = 128; o; o >>= 1) {
        if (t < o) s[t] += s[t + o];
        __syncthreads();
    }
    if (t == 0) {
        float a = s[0] + (g_impsum * invN) * Wt1[(size_t)HD * 256 + j] + bt1[j];
        float h = fmaxf(a, 0.f);
        atomicAdd(&g_tkl[0], h * Wt2[j * 2 + 0]);
        atomicAdd(&g_tkl[1], h * Wt2[j * 2 + 1]);
        if (j == 0) {
            atomicAdd(&g_tkl[0], bt2[0]);
            atomicAdd(&g_tkl[1], bt2[1]);
        }
    }
}

// ---------------------------------------------------------------------------
// router: logits = H1 @ W2 + b2 -> softmax -> probs + top-2. One warp/token.
__global__ __launch_bounds__(256)
void router_kernel(const float* __restrict__ W2, const float* __restrict__ b2,
                   float* __restrict__ out_rp) {
    __shared__ float ps[NE];
    int t = threadIdx.x, warp = t >> 5, lane = t & 31;
    if (t < NE) ps[t] = 0.f;
    __syncthreads();
    int token = blockIdx.x * 8 + warp;
    const float* h = g_H1 + (size_t)token * HD;
    float acc[NE];
#pragma unroll
    for (int e = 0; e < NE; e++) acc[e] = 0.f;
    for (int i = 0; i < HD / 32; i++) {
        int k = lane + 32 * i;
        float hv = h[k];
        const float4* w = (const float4*)(W2 + (size_t)k * NE);
        float4 w0 = __ldg(w + 0), w1 = __ldg(w + 1), w2 = __ldg(w + 2), w3 = __ldg(w + 3);
        acc[0]  += hv * w0.x; acc[1]  += hv * w0.y; acc[2]  += hv * w0.z; acc[3]  += hv * w0.w;
        acc[4]  += hv * w1.x; acc[5]  += hv * w1.y; acc[6]  += hv * w1.z; acc[7]  += hv * w1.w;
        acc[8]  += hv * w2.x; acc[9]  += hv * w2.y; acc[10] += hv * w2.z; acc[11] += hv * w2.w;
        acc[12] += hv * w3.x; acc[13] += hv * w3.y; acc[14] += hv * w3.z; acc[15] += hv * w3.w;
    }
#pragma unroll
    for (int e = 0; e < NE; e++)
#pragma unroll
        for (int o = 16; o; o >>= 1) acc[e] += __shfl_xor_sync(0xffffffffu, acc[e], o);

    if (lane == 0) {
        float p[NE];
        float mx = -1e30f;
#pragma unroll
        for (int e = 0; e < NE; e++) { p[e] = acc[e] + b2[e]; mx = fmaxf(mx, p[e]); }
        float sum = 0.f;
#pragma unroll
        for (int e = 0; e < NE; e++) { p[e] = expf(p[e] - mx); sum += p[e]; }
        float inv = 1.f / sum;
#pragma unroll
        for (int e = 0; e < NE; e++) p[e] *= inv;
#pragma unroll
        for (int e = 0; e < NE; e++) {
            out_rp[(size_t)token * NE + e] = p[e];
            atomicAdd(&ps[e], p[e]);
        }
        int e0 = 0;
#pragma unroll
        for (int e = 1; e < NE; e++) if (p[e] > p[e0]) e0 = e;
        int best = -1; float bv = -1.f;
#pragma unroll
        for (int e = 0; e < NE; e++) {
            if (e == e0) continue;
            if (p[e] > bv) { bv = p[e]; best = e; }
        }
        g_tp[token * 2 + 0] = p[e0];
        g_tp[token * 2 + 1] = p[best];
        g_te[token * 2 + 0] = e0;
        g_te[token * 2 + 1] = best;
    }
    __syncthreads();
    if (t < NE) atomicAdd(&g_probsum[t], ps[t]);
}

// ---------------------------------------------------------------------------
// per-expert parallel scan + scatter: one block per expert (grid = 16)
__global__ __launch_bounds__(256)
void scan_scatter16_kernel(float* __restrict__ out) {
    const int e = blockIdx.x;
    const int t = threadIdx.x;
    const int k = (g_tkl[1] > g_tkl[0]) ? 2 : 1;
    const int cap = 384 * k;
    const int base = t * 32;

    __shared__ int cnt[256];
    int local = 0;
#pragma unroll 4
    for (int i = 0; i < 32; i++) {
        int n = base + i;
        if ((n & 1) < k && g_te[n] == e) local++;
    }
    cnt[t] = local;
    __syncthreads();
    // Hillis-Steele inclusive scan
    for (int off = 1; off < 256; off <<= 1) {
        int v = (t >= off) ? cnt[t - off] : 0;
        __syncthreads();
        cnt[t] += v;
        __syncthreads();
    }
    int total = cnt[255];
    int pos = cnt[t] - local;   // exclusive prefix

    float* disp = out;
    float* comb = out + COMB_OFF;
    const float* imp = out + IMP_OFF;

    for (int i = 0; i < 32; i++) {
        int n = base + i;
        int slot = n & 1;
        if (slot >= k || g_te[n] != e) continue;
        if (pos < cap) {
            int token = n >> 1;
            float tp0 = g_tp[token * 2 + 0];
            float tp1 = g_tp[token * 2 + 1];
            float denom = (k == 2) ? (tp0 + tp1 + 1e-8f) : (tp0 + 1e-8f);
            float pn = ((slot == 0) ? tp0 : tp1) / denom;
            float f = 1.f + ((imp[token] > 0.5f) ? 1.f : 0.f);
            long long off = (long long)token * NE * CAPM + (long long)e * CAPM + pos;
            disp[off] = 1.f;
            comb[off] = pn * f;
        }
        pos++;
    }
    if (t == 0) {
        float invN = 1.f / 4096.f;
        float invA = 1.f / (4096.f * (float)k);
        atomicAdd(&g_aux, (g_probsum[e] * invN) * ((float)total * invA) * (float)NE);
    }
}

__global__ void finalize_kernel(float* __restrict__ out) {
    out[AUX_OFF] = g_aux;
}

// ---------------------------------------------------------------------------
extern "C" void kernel_launch(void* const* d_in, const int* in_sizes, int n_in,
                              void* d_out, int out_size) {
    const float* X   = (const float*)d_in[0];
    const float* W1  = (const float*)d_in[1];
    const float* b1  = (const float*)d_in[2];
    const float* W2  = (const float*)d_in[3];
    const float* b2  = (const float*)d_in[4];
    const float* Wi1 = (const float*)d_in[5];
    const float* bi1 = (const float*)d_in[6];
    const float* Wi2 = (const float*)d_in[7];
    const float* bi2 = (const float*)d_in[8];
    const float* Wt1 = (const float*)d_in[9];
    const float* bt1 = (const float*)d_in[10];
    const float* Wt2 = (const float*)d_in[11];
    const float* bt2 = (const float*)d_in[12];
    float* out = (float*)d_out;

    float *H1p = nullptr, *Hip = nullptr;
    __nv_bfloat16 *A0p = nullptr, *A1p = nullptr, *B0p = nullptr, *B1p = nullptr;
    cudaGetSymbolAddress((void**)&H1p, g_H1);
    cudaGetSymbolAddress((void**)&Hip, g_Hi);
    cudaGetSymbolAddress((void**)&A0p, g_A0);
    cudaGetSymbolAddress((void**)&A1p, g_A1);
    cudaGetSymbolAddress((void**)&B0p, g_B0);
    cudaGetSymbolAddress((void**)&B1p, g_B1);

    cudaFuncSetAttribute(gemm_mma, cudaFuncAttributeMaxDynamicSharedMemorySize, SMEMT);

    static cudaStream_t s1 = nullptr;
    static cudaEvent_t ev0 = nullptr, evA = nullptr, ev1 = nullptr, evG = nullptr, evI = nullptr;
    if (!s1) {
        cudaStreamCreateWithFlags(&s1, cudaStreamNonBlocking);
        cudaEventCreateWithFlags(&ev0, cudaEventDisableTiming);
        cudaEventCreateWithFlags(&evA, cudaEventDisableTiming);
        cudaEventCreateWithFlags(&ev1, cudaEventDisableTiming);
        cudaEventCreateWithFlags(&evG, cudaEventDisableTiming);
        cudaEventCreateWithFlags(&evI, cudaEventDisableTiming);
    }

    // fork side stream
    cudaEventRecord(ev0, 0);
    cudaStreamWaitEvent(s1, ev0, 0);

    // side stream: init accumulators, big zero-fill, column means
    init_small_kernel<<<1, 1024, 0, s1>>>();
    cudaEventRecord(evA, s1);
    zero_out_kernel<<<2048, 256, 0, s1>>>(out, 2 * D_SZ);
    colmean_kernel<<<64, 256, 0, s1>>>(X);
    cudaEventRecord(ev1, s1);

    // main: split-convert operands, HMMA tensor-core GEMM (both GEMMs fused)
    convA_kernel<<<4096, 256>>>(X);
    convB_kernel<<<1536, 256>>>(W1, Wi1);
    gemm_mma<<<dim3(NT / 128, BSZ / 128), 256, SMEMT>>>(A0p, A1p, B0p, B1p, b1, bi1, H1p, Hip);
    cudaEventRecord(evG, 0);

    // side stream (after init + gemm): importance from Hi
    cudaStreamWaitEvent(s1, evG, 0);    // s1 already ordered after evA (init)
    imp_kernel<<<BSZ / 8, 256, 0, s1>>>(Wi2, bi2, out + IMP_OFF);
    cudaEventRecord(evI, s1);

    // main: router (needs accumulators zeroed via evA)
    cudaStreamWaitEvent(0, evA, 0);
    router_kernel<<<BSZ / 8, 256>>>(W2, b2, out + RP_OFF);

    // join: colmean/zero + importance done before tk/scan
    cudaStreamWaitEvent(0, ev1, 0);
    cudaStreamWaitEvent(0, evI, 0);
    tk_matvec_kernel<<<256, 256>>>(Wt1, bt1, Wt2, bt2);
    scan_scatter16_kernel<<<NE, 256>>>(out);
    finalize_kernel<<<1, 1>>>(out);
}

// round 6
// speedup vs baseline: 2.2292x; 1.0297x over previous
#include <cuda_runtime.h>
#include <cuda_bf16.h>
#include <math.h>
#include <cstdint>

// Problem constants
#define BSZ   4096        // B*S tokens
#define HD    1024        // hidden
#define NE    16          // experts
#define CAPM  768         // CAP_MAX
#define HI2   512         // H/2
#define NT    1536        // combined N (W1 | Wi1)

static const long long D_SZ    = (long long)BSZ * NE * CAPM;       // 50331648
static const long long COMB_OFF= D_SZ;
static const long long RP_OFF  = 2 * D_SZ;                         // 100663296
static const long long AUX_OFF = RP_OFF + (long long)BSZ * NE;     // 100728832
static const long long IMP_OFF = AUX_OFF + 1;                      // 100728833

// Scratch (device globals; no cudaMalloc allowed)
__device__ float g_H1[(size_t)BSZ * HD];     // relu(X@W1+b1)   16MB
__device__ float g_Hi[(size_t)BSZ * HI2];    // relu(X@Wi1+bi1)  8MB
__device__ __nv_bfloat16 g_A0[(size_t)BSZ * HD];   // bf16 hi split of X
__device__ __nv_bfloat16 g_A1[(size_t)BSZ * HD];   // bf16 lo split of X
__device__ __nv_bfloat16 g_B0[(size_t)HD * NT];    // bf16 hi split of [W1|Wi1]
__device__ __nv_bfloat16 g_B1[(size_t)HD * NT];    // bf16 lo split
__device__ float g_avg[HD];                  // column sums of X
__device__ float g_impsum;                   // sum of importance
__device__ float g_probsum[NE];              // sum of router probs per expert
__device__ float g_tkl[2];                   // top-k predictor logits
__device__ float g_aux;                      // aux loss accumulator
__device__ float g_tp[BSZ * 2];              // top-2 probs
__device__ int   g_te[BSZ * 2];              // top-2 expert ids

// ===========================================================================
// PTX helpers (portable; nothing sm_103a-suffix-gated)
// ===========================================================================
__device__ __forceinline__ uint32_t smem_to_u32(const void* p) {
    uint32_t a;
    asm("{ .reg .u64 t; cvta.to.shared.u64 t, %1; cvt.u32.u64 %0, t; }" : "=r"(a) : "l"(p));
    return a;
}
#define LDSM4(d, a) \
    asm volatile("ldmatrix.sync.aligned.m8n8.x4.shared.b16 {%0,%1,%2,%3}, [%4];" \
        : "=r"((d)[0]), "=r"((d)[1]), "=r"((d)[2]), "=r"((d)[3]) : "r"(a))
#define LDSM4T(d, a) \
    asm volatile("ldmatrix.sync.aligned.m8n8.x4.trans.shared.b16 {%0,%1,%2,%3}, [%4];" \
        : "=r"((d)[0]), "=r"((d)[1]), "=r"((d)[2]), "=r"((d)[3]) : "r"(a))
#define MMA16816(c, a, b0, b1) \
    asm volatile("mma.sync.aligned.m16n8k16.row.col.f32.bf16.bf16.f32 " \
        "{%0,%1,%2,%3}, {%4,%5,%6,%7}, {%8,%9}, {%0,%1,%2,%3};" \
        : "+f"((c)[0]), "+f"((c)[1]), "+f"((c)[2]), "+f"((c)[3]) \
        : "r"((a)[0]), "r"((a)[1]), "r"((a)[2]), "r"((a)[3]), "r"(b0), "r"(b1))
#define CP16(s, g) \
    asm volatile("cp.async.cg.shared.global [%0], [%1], 16;" :: "r"(s), "l"(g))
#define CP_COMMIT() asm volatile("cp.async.commit_group;" ::: "memory")
#define CP_WAIT1()  asm volatile("cp.async.wait_group 1;" ::: "memory")
#define CP_WAIT0()  asm volatile("cp.async.wait_group 0;" ::: "memory")

// smem geometry (bytes): padded rows for conflict-free ldmatrix
#define AS_ROWB   80                     // 32 bf16 + pad -> 80B rows
#define BS_ROWB   272                    // 128 bf16 + pad -> 272B rows
#define A_SPLIT_B (64 * AS_ROWB)         // 5120
#define B_SPLIT_B (32 * BS_ROWB)         // 8704
#define B_OFF     (2 * A_SPLIT_B)        // 10240
#define BUF_B     (B_OFF + 2 * B_SPLIT_B)// 27648
#define SMEMT     (2 * BUF_B)            // 55296

// ===========================================================================
// fused HMMA bf16-split GEMM: [H1|Hi] = relu(X @ [W1|Wi1] + [b1|bi1])
// grid (12, 64), 256 threads; block tile 64x128, BK=32, warp tile 32x32.
// occ=3 for wave balance. 3 products: A0B0 + A1B0 + A0B1.
// ===========================================================================
__global__ __launch_bounds__(256, 3)
void gemm_mma(const __nv_bfloat16* __restrict__ A0g, const __nv_bfloat16* __restrict__ A1g,
              const __nv_bfloat16* __restrict__ B0g, const __nv_bfloat16* __restrict__ B1g,
              const float* __restrict__ b1, const float* __restrict__ bi1,
              float* __restrict__ H1, float* __restrict__ Hi) {
    extern __shared__ char smem[];
    const uint32_t sb = smem_to_u32(smem);
    const int tid = threadIdx.x, wid = tid >> 5, lane = tid & 31;
    const int m0 = blockIdx.y * 64;
    const int n0 = blockIdx.x * 128;

    // ---- global->smem loaders (cp.async): A 2x16B, B 4x16B per thread ----
    const int ar = tid >> 2, acq = tid & 3;             // A: row 0..63, 16B chunk 0..3
    const int br = tid >> 3, bcq = tid & 7;             // B: row 0..31, 32B chunk 0..7
    const __nv_bfloat16* A0p = A0g + (size_t)(m0 + ar) * HD + acq * 8;
    const __nv_bfloat16* A1p = A1g + (size_t)(m0 + ar) * HD + acq * 8;
    const __nv_bfloat16* B0p = B0g + (size_t)br * NT + n0 + bcq * 16;
    const __nv_bfloat16* B1p = B1g + (size_t)br * NT + n0 + bcq * 16;
    const uint32_t asw = sb + (uint32_t)ar * AS_ROWB + acq * 16;
    const uint32_t bsw = sb + B_OFF + (uint32_t)br * BS_ROWB + bcq * 32;

    auto issue = [&](int it, int buf) {
        const uint32_t a = asw + buf * BUF_B;
        CP16(a,             A0p + it * 32);
        CP16(a + A_SPLIT_B, A1p + it * 32);
        const uint32_t b = bsw + buf * BUF_B;
        const __nv_bfloat16* pb0 = B0p + (size_t)it * 32 * NT;
        const __nv_bfloat16* pb1 = B1p + (size_t)it * 32 * NT;
        CP16(b,                  pb0);
        CP16(b + 16,             pb0 + 8);
        CP16(b + B_SPLIT_B,      pb1);
        CP16(b + B_SPLIT_B + 16, pb1 + 8);
        CP_COMMIT();
    };

    // ---- per-warp ldmatrix base addresses ----
    const int wm = wid >> 2, wn = wid & 3;              // 2 x 4 warp grid
    const int mbase = wm * 32, nbase = wn * 32;
    const int l8 = lane & 7, lb8 = (lane >> 3) & 1, lhi = lane >> 4;
    const uint32_t aAddr = sb + (uint32_t)(mbase + l8 + 8 * lb8) * AS_ROWB + lhi * 16;
    const uint32_t bAddr = sb + B_OFF + (uint32_t)(l8 + 8 * lb8) * BS_ROWB
                         + (uint32_t)(nbase + lhi * 8) * 2;

    float acc[2][4][4];
#pragma unroll
    for (int i = 0; i < 2; i++)
#pragma unroll
        for (int j = 0; j < 4; j++)
#pragma unroll
            for (int c = 0; c < 4; c++) acc[i][j][c] = 0.f;

    issue(0, 0);

    for (int it = 0; it < 32; it++) {
        const int buf = it & 1;
        if (it < 31) { issue(it + 1, buf ^ 1); CP_WAIT1(); }
        else         { CP_WAIT0(); }
        __syncthreads();

        const uint32_t aB = aAddr + buf * BUF_B;
        const uint32_t bB = bAddr + buf * BUF_B;
#pragma unroll
        for (int ks = 0; ks < 2; ks++) {
            const uint32_t aK = aB + ks * 32;            // 16 k-elems = 32 bytes
            const uint32_t bK = bB + ks * 16 * BS_ROWB;  // 16 k-rows
            uint32_t a0f[2][4], a1f[2][4], bf[2][4];
            // A0, B0
#pragma unroll
            for (int ti = 0; ti < 2; ti++) LDSM4(a0f[ti], aK + ti * 16 * AS_ROWB);
#pragma unroll
            for (int nt = 0; nt < 2; nt++) LDSM4T(bf[nt], bK + nt * 32);
#pragma unroll
            for (int ti = 0; ti < 2; ti++)
#pragma unroll
                for (int nj = 0; nj < 4; nj++)
                    MMA16816(acc[ti][nj], a0f[ti], bf[nj >> 1][(nj & 1) * 2], bf[nj >> 1][(nj & 1) * 2 + 1]);
            // A1 x B0 (reuse bf)
#pragma unroll
            for (int ti = 0; ti < 2; ti++) LDSM4(a1f[ti], aK + A_SPLIT_B + ti * 16 * AS_ROWB);
#pragma unroll
            for (int ti = 0; ti < 2; ti++)
#pragma unroll
                for (int nj = 0; nj < 4; nj++)
                    MMA16816(acc[ti][nj], a1f[ti], bf[nj >> 1][(nj & 1) * 2], bf[nj >> 1][(nj & 1) * 2 + 1]);
            // B1 (overwrite bf), A0 x B1
#pragma unroll
            for (int nt = 0; nt < 2; nt++) LDSM4T(bf[nt], bK + B_SPLIT_B + nt * 32);
#pragma unroll
            for (int ti = 0; ti < 2; ti++)
#pragma unroll
                for (int nj = 0; nj < 4; nj++)
                    MMA16816(acc[ti][nj], a0f[ti], bf[nj >> 1][(nj & 1) * 2], bf[nj >> 1][(nj & 1) * 2 + 1]);
        }
        __syncthreads();
    }

    // ---- epilogue: bias + relu, direct global stores ----
    const bool isH1 = (n0 < HD);
    float* dst = isH1 ? H1 : Hi;
    const int stride = isH1 ? HD : HI2;
    const int nadj = isH1 ? n0 : (n0 - HD);
    const float* bias = isH1 ? b1 : bi1;
#pragma unroll
    for (int ti = 0; ti < 2; ti++) {
        const int r0 = m0 + mbase + ti * 16 + (lane >> 2);
#pragma unroll
        for (int nj = 0; nj < 4; nj++) {
            const int cn = nadj + nbase + nj * 8 + (lane & 3) * 2;
            const float bx = __ldg(bias + cn), by = __ldg(bias + cn + 1);
            float2 v0, v1;
            v0.x = fmaxf(acc[ti][nj][0] + bx, 0.f);
            v0.y = fmaxf(acc[ti][nj][1] + by, 0.f);
            v1.x = fmaxf(acc[ti][nj][2] + bx, 0.f);
            v1.y = fmaxf(acc[ti][nj][3] + by, 0.f);
            *(float2*)(dst + (size_t)r0 * stride + cn)       = v0;
            *(float2*)(dst + (size_t)(r0 + 8) * stride + cn) = v1;
        }
    }
}

// ===========================================================================
// pre-pass converters: fp32 -> bf16 split pair
// ===========================================================================
__device__ __forceinline__ void split_bf16(float f, __nv_bfloat16& h0, __nv_bfloat16& h1) {
    h0 = __float2bfloat16_rn(f);
    h1 = __float2bfloat16_rn(f - __bfloat162float(h0));
}

__global__ __launch_bounds__(256)
void convA_kernel(const float* __restrict__ X) {
    size_t i = (size_t)blockIdx.x * 256 + threadIdx.x;   // over 1M float4
    float4 v = ((const float4*)X)[i];
    __nv_bfloat162 a0, a1, b0, b1;
    split_bf16(v.x, a0.x, a1.x); split_bf16(v.y, a0.y, a1.y);
    split_bf16(v.z, b0.x, b1.x); split_bf16(v.w, b0.y, b1.y);
    ((__nv_bfloat162*)g_A0)[2 * i]     = a0;
    ((__nv_bfloat162*)g_A0)[2 * i + 1] = b0;
    ((__nv_bfloat162*)g_A1)[2 * i]     = a1;
    ((__nv_bfloat162*)g_A1)[2 * i + 1] = b1;
}

__global__ __launch_bounds__(256)
void convB_kernel(const float* __restrict__ W1, const float* __restrict__ Wi1) {
    size_t i = (size_t)blockIdx.x * 256 + threadIdx.x;   // over 1024*1536/4 float4
    int r = (int)(i / 384);
    int c = (int)(i % 384) * 4;
    float4 v = (c < HD) ? *(const float4*)(W1 + (size_t)r * HD + c)
                        : *(const float4*)(Wi1 + (size_t)r * HI2 + c - HD);
    __nv_bfloat162 a0, a1, b0, b1;
    split_bf16(v.x, a0.x, a1.x); split_bf16(v.y, a0.y, a1.y);
    split_bf16(v.z, b0.x, b1.x); split_bf16(v.w, b0.y, b1.y);
    ((__nv_bfloat162*)g_B0)[2 * i]     = a0;
    ((__nv_bfloat162*)g_B0)[2 * i + 1] = b0;
    ((__nv_bfloat162*)g_B1)[2 * i]     = a1;
    ((__nv_bfloat162*)g_B1)[2 * i + 1] = b1;
}

// ===========================================================================
__global__ void zero_out_kernel(float* __restrict__ out, long long n) {
    long long stride = (long long)gridDim.x * blockDim.x;
    long long i = (long long)blockIdx.x * blockDim.x + threadIdx.x;
    long long n4 = n >> 2;
    float4 z = make_float4(0.f, 0.f, 0.f, 0.f);
    for (long long j = i; j < n4; j += stride)
        ((float4*)out)[j] = z;
}

__global__ void init_small_kernel() {
    int t = threadIdx.x;
    if (t < HD) g_avg[t] = 0.f;
    if (t < NE) g_probsum[t] = 0.f;
    if (t == 0) { g_impsum = 0.f; g_aux = 0.f; }
    if (t < 2) g_tkl[t] = 0.f;
}

// ---------------------------------------------------------------------------
// importance = sigmoid(Hi @ Wi2 + bi2); one warp per token
__global__ __launch_bounds__(256)
void imp_kernel(const float* __restrict__ Wi2, const float* __restrict__ bi2,
                float* __restrict__ out_imp) {
    __shared__ float w[HI2];
    int t = threadIdx.x;
    w[t] = Wi2[t];
    w[t + 256] = Wi2[t + 256];
    __syncthreads();
    int warp = t >> 5, lane = t & 31;
    int token = blockIdx.x * 8 + warp;
    const float* h = g_Hi + (size_t)token * HI2;
    float acc = 0.f;
#pragma unroll
    for (int i = 0; i < HI2 / 32; i++)
        acc += h[lane + 32 * i] * w[lane + 32 * i];
#pragma unroll
    for (int o = 16; o; o >>= 1) acc += __shfl_xor_sync(0xffffffffu, acc, o);
    if (lane == 0) {
        float v = 1.f / (1.f + expf(-(acc + bi2[0])));
        out_imp[token] = v;
        atomicAdd(&g_impsum, v);
    }
}

// column sums of X -> g_avg
__global__ __launch_bounds__(256)
void colmean_kernel(const float* __restrict__ X) {
    int t = threadIdx.x;
    int r0 = blockIdx.x * 64;
    float4 s = make_float4(0.f, 0.f, 0.f, 0.f);
    for (int r = r0; r < r0 + 64; r++) {
        float4 v = ((const float4*)X)[(size_t)r * 256 + t];
        s.x += v.x; s.y += v.y; s.z += v.z; s.w += v.w;
    }
    atomicAdd(&g_avg[t * 4 + 0], s.x);
    atomicAdd(&g_avg[t * 4 + 1], s.y);
    atomicAdd(&g_avg[t * 4 + 2], s.z);
    atomicAdd(&g_avg[t * 4 + 3], s.w);
}

// top-k predictor matvec: block j computes hidden unit j, accumulates logits
__global__ __launch_bounds__(256)
void tk_matvec_kernel(const float* __restrict__ Wt1, const float* __restrict__ bt1,
                      const float* __restrict__ Wt2, const float* __restrict__ bt2) {
    int j = blockIdx.x, t = threadIdx.x;
    const float invN = 1.f / 4096.f;
    float acc = 0.f;
    for (int i = t; i < HD; i += 256)
        acc += (g_avg[i] * invN) * Wt1[(size_t)i * 256 + j];
    __shared__ float s[256];
    s[t] = acc;
    __syncthreads();
    for (int o = 128; o; o >>= 1) {
        if (t < o) s[t] += s[t + o];
        __syncthreads();
    }
    if (t == 0) {
        float a = s[0] + (g_impsum * invN) * Wt1[(size_t)HD * 256 + j] + bt1[j];
        float h = fmaxf(a, 0.f);
        atomicAdd(&g_tkl[0], h * Wt2[j * 2 + 0]);
        atomicAdd(&g_tkl[1], h * Wt2[j * 2 + 1]);
        if (j == 0) {
            atomicAdd(&g_tkl[0], bt2[0]);
            atomicAdd(&g_tkl[1], bt2[1]);
        }
    }
}

// ---------------------------------------------------------------------------
// router: logits = H1 @ W2 + b2 -> softmax -> probs + top-2. One warp/token.
__global__ __launch_bounds__(256)
void router_kernel(const float* __restrict__ W2, const float* __restrict__ b2,
                   float* __restrict__ out_rp) {
    __shared__ float ps[NE];
    int t = threadIdx.x, warp = t >> 5, lane = t & 31;
    if (t < NE) ps[t] = 0.f;
    __syncthreads();
    int token = blockIdx.x * 8 + warp;
    const float* h = g_H1 + (size_t)token * HD;
    float acc[NE];
#pragma unroll
    for (int e = 0; e < NE; e++) acc[e] = 0.f;
    for (int i = 0; i < HD / 32; i++) {
        int k = lane + 32 * i;
        float hv = h[k];
        const float4* w = (const float4*)(W2 + (size_t)k * NE);
        float4 w0 = __ldg(w + 0), w1 = __ldg(w + 1), w2 = __ldg(w + 2), w3 = __ldg(w + 3);
        acc[0]  += hv * w0.x; acc[1]  += hv * w0.y; acc[2]  += hv * w0.z; acc[3]  += hv * w0.w;
        acc[4]  += hv * w1.x; acc[5]  += hv * w1.y; acc[6]  += hv * w1.z; acc[7]  += hv * w1.w;
        acc[8]  += hv * w2.x; acc[9]  += hv * w2.y; acc[10] += hv * w2.z; acc[11] += hv * w2.w;
        acc[12] += hv * w3.x; acc[13] += hv * w3.y; acc[14] += hv * w3.z; acc[15] += hv * w3.w;
    }
#pragma unroll
    for (int e = 0; e < NE; e++)
#pragma unroll
        for (int o = 16; o; o >>= 1) acc[e] += __shfl_xor_sync(0xffffffffu, acc[e], o);

    if (lane == 0) {
        float p[NE];
        float mx = -1e30f;
#pragma unroll
        for (int e = 0; e < NE; e++) { p[e] = acc[e] + b2[e]; mx = fmaxf(mx, p[e]); }
        float sum = 0.f;
#pragma unroll
        for (int e = 0; e < NE; e++) { p[e] = expf(p[e] - mx); sum += p[e]; }
        float inv = 1.f / sum;
#pragma unroll
        for (int e = 0; e < NE; e++) p[e] *= inv;
#pragma unroll
        for (int e = 0; e < NE; e++) {
            out_rp[(size_t)token * NE + e] = p[e];
            atomicAdd(&ps[e], p[e]);
        }
        int e0 = 0;
#pragma unroll
        for (int e = 1; e < NE; e++) if (p[e] > p[e0]) e0 = e;
        int best = -1; float bv = -1.f;
#pragma unroll
        for (int e = 0; e < NE; e++) {
            if (e == e0) continue;
            if (p[e] > bv) { bv = p[e]; best = e; }
        }
        g_tp[token * 2 + 0] = p[e0];
        g_tp[token * 2 + 1] = p[best];
        g_te[token * 2 + 0] = e0;
        g_te[token * 2 + 1] = best;
    }
    __syncthreads();
    if (t < NE) atomicAdd(&g_probsum[t], ps[t]);
}

// ---------------------------------------------------------------------------
// per-expert parallel scan + scatter: one block per expert (grid = 16)
__global__ __launch_bounds__(256)
void scan_scatter16_kernel(float* __restrict__ out) {
    const int e = blockIdx.x;
    const int t = threadIdx.x;
    const int k = (g_tkl[1] > g_tkl[0]) ? 2 : 1;
    const int cap = 384 * k;
    const int base = t * 32;

    __shared__ int cnt[256];
    int local = 0;
#pragma unroll 4
    for (int i = 0; i < 32; i++) {
        int n = base + i;
        if ((n & 1) < k && g_te[n] == e) local++;
    }
    cnt[t] = local;
    __syncthreads();
    for (int off = 1; off < 256; off <<= 1) {
        int v = (t >= off) ? cnt[t - off] : 0;
        __syncthreads();
        cnt[t] += v;
        __syncthreads();
    }
    int total = cnt[255];
    int pos = cnt[t] - local;   // exclusive prefix

    float* disp = out;
    float* comb = out + COMB_OFF;
    const float* imp = out + IMP_OFF;

    for (int i = 0; i < 32; i++) {
        int n = base + i;
        int slot = n & 1;
        if (slot >= k || g_te[n] != e) continue;
        if (pos < cap) {
            int token = n >> 1;
            float tp0 = g_tp[token * 2 + 0];
            float tp1 = g_tp[token * 2 + 1];
            float denom = (k == 2) ? (tp0 + tp1 + 1e-8f) : (tp0 + 1e-8f);
            float pn = ((slot == 0) ? tp0 : tp1) / denom;
            float f = 1.f + ((imp[token] > 0.5f) ? 1.f : 0.f);
            long long off = (long long)token * NE * CAPM + (long long)e * CAPM + pos;
            disp[off] = 1.f;
            comb[off] = pn * f;
        }
        pos++;
    }
    if (t == 0) {
        float invN = 1.f / 4096.f;
        float invA = 1.f / (4096.f * (float)k);
        atomicAdd(&g_aux, (g_probsum[e] * invN) * ((float)total * invA) * (float)NE);
    }
}

__global__ void finalize_kernel(float* __restrict__ out) {
    out[AUX_OFF] = g_aux;
}

// ---------------------------------------------------------------------------
extern "C" void kernel_launch(void* const* d_in, const int* in_sizes, int n_in,
                              void* d_out, int out_size) {
    const float* X   = (const float*)d_in[0];
    const float* W1  = (const float*)d_in[1];
    const float* b1  = (const float*)d_in[2];
    const float* W2  = (const float*)d_in[3];
    const float* b2  = (const float*)d_in[4];
    const float* Wi1 = (const float*)d_in[5];
    const float* bi1 = (const float*)d_in[6];
    const float* Wi2 = (const float*)d_in[7];
    const float* bi2 = (const float*)d_in[8];
    const float* Wt1 = (const float*)d_in[9];
    const float* bt1 = (const float*)d_in[10];
    const float* Wt2 = (const float*)d_in[11];
    const float* bt2 = (const float*)d_in[12];
    float* out = (float*)d_out;

    float *H1p = nullptr, *Hip = nullptr;
    __nv_bfloat16 *A0p = nullptr, *A1p = nullptr, *B0p = nullptr, *B1p = nullptr;
    cudaGetSymbolAddress((void**)&H1p, g_H1);
    cudaGetSymbolAddress((void**)&Hip, g_Hi);
    cudaGetSymbolAddress((void**)&A0p, g_A0);
    cudaGetSymbolAddress((void**)&A1p, g_A1);
    cudaGetSymbolAddress((void**)&B0p, g_B0);
    cudaGetSymbolAddress((void**)&B1p, g_B1);

    cudaFuncSetAttribute(gemm_mma, cudaFuncAttributeMaxDynamicSharedMemorySize, SMEMT);

    static cudaStream_t s1 = nullptr;
    static cudaEvent_t ev0 = nullptr, evB = nullptr, ev1 = nullptr, evG = nullptr, evI = nullptr;
    if (!s1) {
        cudaStreamCreateWithFlags(&s1, cudaStreamNonBlocking);
        cudaEventCreateWithFlags(&ev0, cudaEventDisableTiming);
        cudaEventCreateWithFlags(&evB, cudaEventDisableTiming);
        cudaEventCreateWithFlags(&ev1, cudaEventDisableTiming);
        cudaEventCreateWithFlags(&evG, cudaEventDisableTiming);
        cudaEventCreateWithFlags(&evI, cudaEventDisableTiming);
    }

    // main: convert X (launch #1)
    convA_kernel<<<4096, 256>>>(X);

    // fork side stream
    cudaEventRecord(ev0, 0);
    cudaStreamWaitEvent(s1, ev0, 0);

    // side stream: init (#2), convB (#3), then big zero-fill (#4), colmean (#5)
    init_small_kernel<<<1, 1024, 0, s1>>>();
    convB_kernel<<<1536, 256, 0, s1>>>(W1, Wi1);
    cudaEventRecord(evB, s1);                       // init + convB done
    zero_out_kernel<<<2048, 256, 0, s1>>>(out, 2 * D_SZ);
    colmean_kernel<<<64, 256, 0, s1>>>(X);
    cudaEventRecord(ev1, s1);                       // zero + colmean done

    // main: GEMM (launch #6 — ncu -s 5 -c 1 captures this)
    cudaStreamWaitEvent(0, evB, 0);
    gemm_mma<<<dim3(NT / 128, BSZ / 64), 256, SMEMT>>>(A0p, A1p, B0p, B1p, b1, bi1, H1p, Hip);
    cudaEventRecord(evG, 0);

    // side stream: importance from Hi (hidden behind router)
    cudaStreamWaitEvent(s1, evG, 0);
    imp_kernel<<<BSZ / 8, 256, 0, s1>>>(Wi2, bi2, out + IMP_OFF);
    cudaEventRecord(evI, s1);

    // main: router
    router_kernel<<<BSZ / 8, 256>>>(W2, b2, out + RP_OFF);

    // join: colmean/zero + importance done before tk/scan
    cudaStreamWaitEvent(0, ev1, 0);
    cudaStreamWaitEvent(0, evI, 0);
    tk_matvec_kernel<<<256, 256>>>(Wt1, bt1, Wt2, bt2);
    scan_scatter16_kernel<<<NE, 256>>>(out);
    finalize_kernel<<<1, 1>>>(out);
}

// round 7
// speedup vs baseline: 2.5470x; 1.1425x over previous
#include <cuda_runtime.h>
#include <cuda_bf16.h>
#include <math.h>
#include <cstdint>

// Problem constants
#define BSZ   4096        // B*S tokens
#define HD    1024        // hidden
#define NE    16          // experts
#define CAPM  768         // CAP_MAX
#define HI2   512         // H/2
#define NT    1536        // combined N (W1 | Wi1)

static const long long D_SZ    = (long long)BSZ * NE * CAPM;       // 50331648
static const long long COMB_OFF= D_SZ;
static const long long RP_OFF  = 2 * D_SZ;                         // 100663296
static const long long AUX_OFF = RP_OFF + (long long)BSZ * NE;     // 100728832
static const long long IMP_OFF = AUX_OFF + 1;                      // 100728833

// Scratch (device globals; no cudaMalloc allowed)
__device__ float g_H1[(size_t)BSZ * HD];     // relu(X@W1+b1)   16MB
__device__ float g_Hi[(size_t)BSZ * HI2];    // relu(X@Wi1+bi1)  8MB
__device__ __nv_bfloat16 g_A0[(size_t)BSZ * HD];   // bf16 hi split of X
__device__ __nv_bfloat16 g_A1[(size_t)BSZ * HD];   // bf16 lo split of X
__device__ __nv_bfloat16 g_B0[(size_t)HD * NT];    // bf16 hi split of [W1|Wi1]
__device__ __nv_bfloat16 g_B1[(size_t)HD * NT];    // bf16 lo split
__device__ float g_avg[HD];                  // column sums of X
__device__ float g_impsum;                   // sum of importance
__device__ float g_probsum[NE];              // sum of router probs per expert
__device__ float g_tkl[2];                   // top-k predictor logits
__device__ float g_aux;                      // aux loss accumulator
__device__ float g_tp[BSZ * 2];              // top-2 probs
__device__ int   g_te[BSZ * 2];              // top-2 expert ids

// ===========================================================================
// PTX helpers (portable; nothing sm_103a-suffix-gated)
// ===========================================================================
__device__ __forceinline__ uint32_t smem_to_u32(const void* p) {
    uint32_t a;
    asm("{ .reg .u64 t; cvta.to.shared.u64 t, %1; cvt.u32.u64 %0, t; }" : "=r"(a) : "l"(p));
    return a;
}
#define LDSM4(d, a) \
    asm volatile("ldmatrix.sync.aligned.m8n8.x4.shared.b16 {%0,%1,%2,%3}, [%4];" \
        : "=r"((d)[0]), "=r"((d)[1]), "=r"((d)[2]), "=r"((d)[3]) : "r"(a))
#define LDSM4T(d, a) \
    asm volatile("ldmatrix.sync.aligned.m8n8.x4.trans.shared.b16 {%0,%1,%2,%3}, [%4];" \
        : "=r"((d)[0]), "=r"((d)[1]), "=r"((d)[2]), "=r"((d)[3]) : "r"(a))
#define MMA16816(c, a, b0, b1) \
    asm volatile("mma.sync.aligned.m16n8k16.row.col.f32.bf16.bf16.f32 " \
        "{%0,%1,%2,%3}, {%4,%5,%6,%7}, {%8,%9}, {%0,%1,%2,%3};" \
        : "+f"((c)[0]), "+f"((c)[1]), "+f"((c)[2]), "+f"((c)[3]) \
        : "r"((a)[0]), "r"((a)[1]), "r"((a)[2]), "r"((a)[3]), "r"(b0), "r"(b1))
#define CP16(s, g) \
    asm volatile("cp.async.cg.shared.global [%0], [%1], 16;" :: "r"(s), "l"(g))
#define CP_COMMIT() asm volatile("cp.async.commit_group;" ::: "memory")
#define CP_WAIT1()  asm volatile("cp.async.wait_group 1;" ::: "memory")
#define CP_WAIT0()  asm volatile("cp.async.wait_group 0;" ::: "memory")

// smem geometry (bytes): padded rows for conflict-free ldmatrix
#define AS_ROWB   80                     // 32 bf16 + pad -> 80B rows
#define BS_ROWB   272                    // 128 bf16 + pad -> 272B rows
#define A_SPLIT_B (64 * AS_ROWB)         // 5120
#define B_SPLIT_B (32 * BS_ROWB)         // 8704
#define B_OFF     (2 * A_SPLIT_B)        // 10240
#define BUF_B     (B_OFF + 2 * B_SPLIT_B)// 27648
#define STAGES    3
#define SMEMT     (STAGES * BUF_B)       // 82944

// ===========================================================================
// fused HMMA bf16-split GEMM: [H1|Hi] = relu(X @ [W1|Wi1] + [b1|bi1])
// grid (12, 64), 256 threads; block tile 64x128, BK=32, warp tile 32x32.
// 3-stage cp.async pipeline, ONE barrier per k-iter, occ=2.
// 3 products: A0B0 + A1B0 + A0B1.
// ===========================================================================
__global__ __launch_bounds__(256, 2)
void gemm_mma(const __nv_bfloat16* __restrict__ A0g, const __nv_bfloat16* __restrict__ A1g,
              const __nv_bfloat16* __restrict__ B0g, const __nv_bfloat16* __restrict__ B1g,
              const float* __restrict__ b1, const float* __restrict__ bi1,
              float* __restrict__ H1, float* __restrict__ Hi) {
    extern __shared__ char smem[];
    const uint32_t sb = smem_to_u32(smem);
    const int tid = threadIdx.x, wid = tid >> 5, lane = tid & 31;
    const int m0 = blockIdx.y * 64;
    const int n0 = blockIdx.x * 128;

    // ---- global->smem loaders (cp.async): A 2x16B, B 4x16B per thread ----
    const int ar = tid >> 2, acq = tid & 3;             // A: row 0..63, 16B chunk 0..3
    const int br = tid >> 3, bcq = tid & 7;             // B: row 0..31, 32B chunk 0..7
    const __nv_bfloat16* A0p = A0g + (size_t)(m0 + ar) * HD + acq * 8;
    const __nv_bfloat16* A1p = A1g + (size_t)(m0 + ar) * HD + acq * 8;
    const __nv_bfloat16* B0p = B0g + (size_t)br * NT + n0 + bcq * 16;
    const __nv_bfloat16* B1p = B1g + (size_t)br * NT + n0 + bcq * 16;
    const uint32_t asw = sb + (uint32_t)ar * AS_ROWB + acq * 16;
    const uint32_t bsw = sb + B_OFF + (uint32_t)br * BS_ROWB + bcq * 32;

    auto issue = [&](int it, int stg) {
        const uint32_t a = asw + stg * BUF_B;
        CP16(a,             A0p + it * 32);
        CP16(a + A_SPLIT_B, A1p + it * 32);
        const uint32_t b = bsw + stg * BUF_B;
        const __nv_bfloat16* pb0 = B0p + (size_t)it * 32 * NT;
        const __nv_bfloat16* pb1 = B1p + (size_t)it * 32 * NT;
        CP16(b,                  pb0);
        CP16(b + 16,             pb0 + 8);
        CP16(b + B_SPLIT_B,      pb1);
        CP16(b + B_SPLIT_B + 16, pb1 + 8);
        CP_COMMIT();
    };

    // ---- per-warp ldmatrix base addresses ----
    const int wm = wid >> 2, wn = wid & 3;              // 2 x 4 warp grid
    const int mbase = wm * 32, nbase = wn * 32;
    const int l8 = lane & 7, lb8 = (lane >> 3) & 1, lhi = lane >> 4;
    const uint32_t aAddr = sb + (uint32_t)(mbase + l8 + 8 * lb8) * AS_ROWB + lhi * 16;
    const uint32_t bAddr = sb + B_OFF + (uint32_t)(l8 + 8 * lb8) * BS_ROWB
                         + (uint32_t)(nbase + lhi * 8) * 2;

    float acc[2][4][4];
#pragma unroll
    for (int i = 0; i < 2; i++)
#pragma unroll
        for (int j = 0; j < 4; j++)
#pragma unroll
            for (int c = 0; c < 4; c++) acc[i][j][c] = 0.f;

    issue(0, 0);
    issue(1, 1);

    int stg = 0;
    for (int it = 0; it < 32; it++) {
        if (it < 30) CP_WAIT1(); else CP_WAIT0();
        __syncthreads();                 // protects stage reuse AND data-ready
        if (it < 30) issue(it + 2, (it + 2) % STAGES);

        const uint32_t aB = aAddr + stg * BUF_B;
        const uint32_t bB = bAddr + stg * BUF_B;
#pragma unroll
        for (int ks = 0; ks < 2; ks++) {
            const uint32_t aK = aB + ks * 32;            // 16 k-elems = 32 bytes
            const uint32_t bK = bB + ks * 16 * BS_ROWB;  // 16 k-rows
            uint32_t a0f[2][4], a1f[2][4], bf[2][4];
            // A0, B0
#pragma unroll
            for (int ti = 0; ti < 2; ti++) LDSM4(a0f[ti], aK + ti * 16 * AS_ROWB);
#pragma unroll
            for (int nt = 0; nt < 2; nt++) LDSM4T(bf[nt], bK + nt * 32);
#pragma unroll
            for (int ti = 0; ti < 2; ti++)
#pragma unroll
                for (int nj = 0; nj < 4; nj++)
                    MMA16816(acc[ti][nj], a0f[ti], bf[nj >> 1][(nj & 1) * 2], bf[nj >> 1][(nj & 1) * 2 + 1]);
            // A1 x B0 (reuse bf)
#pragma unroll
            for (int ti = 0; ti < 2; ti++) LDSM4(a1f[ti], aK + A_SPLIT_B + ti * 16 * AS_ROWB);
#pragma unroll
            for (int ti = 0; ti < 2; ti++)
#pragma unroll
                for (int nj = 0; nj < 4; nj++)
                    MMA16816(acc[ti][nj], a1f[ti], bf[nj >> 1][(nj & 1) * 2], bf[nj >> 1][(nj & 1) * 2 + 1]);
            // B1 (overwrite bf), A0 x B1
#pragma unroll
            for (int nt = 0; nt < 2; nt++) LDSM4T(bf[nt], bK + B_SPLIT_B + nt * 32);
#pragma unroll
            for (int ti = 0; ti < 2; ti++)
#pragma unroll
                for (int nj = 0; nj < 4; nj++)
                    MMA16816(acc[ti][nj], a0f[ti], bf[nj >> 1][(nj & 1) * 2], bf[nj >> 1][(nj & 1) * 2 + 1]);
        }
        stg = (stg == STAGES - 1) ? 0 : stg + 1;
    }

    // ---- epilogue: bias + relu, direct global stores ----
    const bool isH1 = (n0 < HD);
    float* dst = isH1 ? H1 : Hi;
    const int stride = isH1 ? HD : HI2;
    const int nadj = isH1 ? n0 : (n0 - HD);
    const float* bias = isH1 ? b1 : bi1;
#pragma unroll
    for (int ti = 0; ti < 2; ti++) {
        const int r0 = m0 + mbase + ti * 16 + (lane >> 2);
#pragma unroll
        for (int nj = 0; nj < 4; nj++) {
            const int cn = nadj + nbase + nj * 8 + (lane & 3) * 2;
            const float bx = __ldg(bias + cn), by = __ldg(bias + cn + 1);
            float2 v0, v1;
            v0.x = fmaxf(acc[ti][nj][0] + bx, 0.f);
            v0.y = fmaxf(acc[ti][nj][1] + by, 0.f);
            v1.x = fmaxf(acc[ti][nj][2] + bx, 0.f);
            v1.y = fmaxf(acc[ti][nj][3] + by, 0.f);
            *(float2*)(dst + (size_t)r0 * stride + cn)       = v0;
            *(float2*)(dst + (size_t)(r0 + 8) * stride + cn) = v1;
        }
    }
}

// ===========================================================================
// pre-pass converters: fp32 -> bf16 split pair
// ===========================================================================
__device__ __forceinline__ void split_bf16(float f, __nv_bfloat16& h0, __nv_bfloat16& h1) {
    h0 = __float2bfloat16_rn(f);
    h1 = __float2bfloat16_rn(f - __bfloat162float(h0));
}

__global__ __launch_bounds__(256)
void convA_kernel(const float* __restrict__ X) {
    size_t i = (size_t)blockIdx.x * 256 + threadIdx.x;   // over 1M float4
    float4 v = ((const float4*)X)[i];
    __nv_bfloat162 a0, a1, b0, b1;
    split_bf16(v.x, a0.x, a1.x); split_bf16(v.y, a0.y, a1.y);
    split_bf16(v.z, b0.x, b1.x); split_bf16(v.w, b0.y, b1.y);
    ((__nv_bfloat162*)g_A0)[2 * i]     = a0;
    ((__nv_bfloat162*)g_A0)[2 * i + 1] = b0;
    ((__nv_bfloat162*)g_A1)[2 * i]     = a1;
    ((__nv_bfloat162*)g_A1)[2 * i + 1] = b1;
}

__global__ __launch_bounds__(256)
void convB_kernel(const float* __restrict__ W1, const float* __restrict__ Wi1) {
    size_t i = (size_t)blockIdx.x * 256 + threadIdx.x;   // over 1024*1536/4 float4
    int r = (int)(i / 384);
    int c = (int)(i % 384) * 4;
    float4 v = (c < HD) ? *(const float4*)(W1 + (size_t)r * HD + c)
                        : *(const float4*)(Wi1 + (size_t)r * HI2 + c - HD);
    __nv_bfloat162 a0, a1, b0, b1;
    split_bf16(v.x, a0.x, a1.x); split_bf16(v.y, a0.y, a1.y);
    split_bf16(v.z, b0.x, b1.x); split_bf16(v.w, b0.y, b1.y);
    ((__nv_bfloat162*)g_B0)[2 * i]     = a0;
    ((__nv_bfloat162*)g_B0)[2 * i + 1] = b0;
    ((__nv_bfloat162*)g_B1)[2 * i]     = a1;
    ((__nv_bfloat162*)g_B1)[2 * i + 1] = b1;
}

// ===========================================================================
// zero dispatch+combine region; streaming (evict-first) stores keep L2 clean
__global__ void zero_out_kernel(float* __restrict__ out, long long n) {
    long long stride = (long long)gridDim.x * blockDim.x;
    long long i = (long long)blockIdx.x * blockDim.x + threadIdx.x;
    long long n4 = n >> 2;
    float4 z = make_float4(0.f, 0.f, 0.f, 0.f);
    for (long long j = i; j < n4; j += stride)
        __stcs(&((float4*)out)[j], z);
}

__global__ void init_small_kernel() {
    int t = threadIdx.x;
    if (t < HD) g_avg[t] = 0.f;
    if (t < NE) g_probsum[t] = 0.f;
    if (t == 0) { g_impsum = 0.f; g_aux = 0.f; }
    if (t < 2) g_tkl[t] = 0.f;
}

// ---------------------------------------------------------------------------
// importance = sigmoid(Hi @ Wi2 + bi2); one warp per token
__global__ __launch_bounds__(256)
void imp_kernel(const float* __restrict__ Wi2, const float* __restrict__ bi2,
                float* __restrict__ out_imp) {
    __shared__ float w[HI2];
    int t = threadIdx.x;
    w[t] = Wi2[t];
    w[t + 256] = Wi2[t + 256];
    __syncthreads();
    int warp = t >> 5, lane = t & 31;
    int token = blockIdx.x * 8 + warp;
    const float* h = g_Hi + (size_t)token * HI2;
    float acc = 0.f;
#pragma unroll
    for (int i = 0; i < HI2 / 32; i++)
        acc += h[lane + 32 * i] * w[lane + 32 * i];
#pragma unroll
    for (int o = 16; o; o >>= 1) acc += __shfl_xor_sync(0xffffffffu, acc, o);
    if (lane == 0) {
        float v = 1.f / (1.f + expf(-(acc + bi2[0])));
        out_imp[token] = v;
        atomicAdd(&g_impsum, v);
    }
}

// column sums of X -> g_avg
__global__ __launch_bounds__(256)
void colmean_kernel(const float* __restrict__ X) {
    int t = threadIdx.x;
    int r0 = blockIdx.x * 64;
    float4 s = make_float4(0.f, 0.f, 0.f, 0.f);
    for (int r = r0; r < r0 + 64; r++) {
        float4 v = ((const float4*)X)[(size_t)r * 256 + t];
        s.x += v.x; s.y += v.y; s.z += v.z; s.w += v.w;
    }
    atomicAdd(&g_avg[t * 4 + 0], s.x);
    atomicAdd(&g_avg[t * 4 + 1], s.y);
    atomicAdd(&g_avg[t * 4 + 2], s.z);
    atomicAdd(&g_avg[t * 4 + 3], s.w);
}

// top-k predictor matvec: block j computes hidden unit j, accumulates logits
__global__ __launch_bounds__(256)
void tk_matvec_kernel(const float* __restrict__ Wt1, const float* __restrict__ bt1,
                      const float* __restrict__ Wt2, const float* __restrict__ bt2) {
    int j = blockIdx.x, t = threadIdx.x;
    const float invN = 1.f / 4096.f;
    float acc = 0.f;
    for (int i = t; i < HD; i += 256)
        acc += (g_avg[i] * invN) * Wt1[(size_t)i * 256 + j];
    __shared__ float s[256];
    s[t] = acc;
    __syncthreads();
    for (int o = 128; o; o >>= 1) {
        if (t < o) s[t] += s[t + o];
        __syncthreads();
    }
    if (t == 0) {
        float a = s[0] + (g_impsum * invN) * Wt1[(size_t)HD * 256 + j] + bt1[j];
        float h = fmaxf(a, 0.f);
        atomicAdd(&g_tkl[0], h * Wt2[j * 2 + 0]);
        atomicAdd(&g_tkl[1], h * Wt2[j * 2 + 1]);
        if (j == 0) {
            atomicAdd(&g_tkl[0], bt2[0]);
            atomicAdd(&g_tkl[1], bt2[1]);
        }
    }
}

// ---------------------------------------------------------------------------
// router: logits = H1 @ W2 + b2 -> softmax -> probs + top-2. One warp/token.
__global__ __launch_bounds__(256)
void router_kernel(const float* __restrict__ W2, const float* __restrict__ b2,
                   float* __restrict__ out_rp) {
    __shared__ float ps[NE];
    int t = threadIdx.x, warp = t >> 5, lane = t & 31;
    if (t < NE) ps[t] = 0.f;
    __syncthreads();
    int token = blockIdx.x * 8 + warp;
    const float* h = g_H1 + (size_t)token * HD;
    float acc[NE];
#pragma unroll
    for (int e = 0; e < NE; e++) acc[e] = 0.f;
    for (int i = 0; i < HD / 32; i++) {
        int k = lane + 32 * i;
        float hv = h[k];
        const float4* w = (const float4*)(W2 + (size_t)k * NE);
        float4 w0 = __ldg(w + 0), w1 = __ldg(w + 1), w2 = __ldg(w + 2), w3 = __ldg(w + 3);
        acc[0]  += hv * w0.x; acc[1]  += hv * w0.y; acc[2]  += hv * w0.z; acc[3]  += hv * w0.w;
        acc[4]  += hv * w1.x; acc[5]  += hv * w1.y; acc[6]  += hv * w1.z; acc[7]  += hv * w1.w;
        acc[8]  += hv * w2.x; acc[9]  += hv * w2.y; acc[10] += hv * w2.z; acc[11] += hv * w2.w;
        acc[12] += hv * w3.x; acc[13] += hv * w3.y; acc[14] += hv * w3.z; acc[15] += hv * w3.w;
    }
#pragma unroll
    for (int e = 0; e < NE; e++)
#pragma unroll
        for (int o = 16; o; o >>= 1) acc[e] += __shfl_xor_sync(0xffffffffu, acc[e], o);

    if (lane == 0) {
        float p[NE];
        float mx = -1e30f;
#pragma unroll
        for (int e = 0; e < NE; e++) { p[e] = acc[e] + b2[e]; mx = fmaxf(mx, p[e]); }
        float sum = 0.f;
#pragma unroll
        for (int e = 0; e < NE; e++) { p[e] = expf(p[e] - mx); sum += p[e]; }
        float inv = 1.f / sum;
#pragma unroll
        for (int e = 0; e < NE; e++) p[e] *= inv;
#pragma unroll
        for (int e = 0; e < NE; e++) {
            out_rp[(size_t)token * NE + e] = p[e];
            atomicAdd(&ps[e], p[e]);
        }
        int e0 = 0;
#pragma unroll
        for (int e = 1; e < NE; e++) if (p[e] > p[e0]) e0 = e;
        int best = -1; float bv = -1.f;
#pragma unroll
        for (int e = 0; e < NE; e++) {
            if (e == e0) continue;
            if (p[e] > bv) { bv = p[e]; best = e; }
        }
        g_tp[token * 2 + 0] = p[e0];
        g_tp[token * 2 + 1] = p[best];
        g_te[token * 2 + 0] = e0;
        g_te[token * 2 + 1] = best;
    }
    __syncthreads();
    if (t < NE) atomicAdd(&g_probsum[t], ps[t]);
}

// ---------------------------------------------------------------------------
// per-expert parallel scan + scatter: one block per expert (grid = 16)
__global__ __launch_bounds__(256)
void scan_scatter16_kernel(float* __restrict__ out) {
    const int e = blockIdx.x;
    const int t = threadIdx.x;
    const int k = (g_tkl[1] > g_tkl[0]) ? 2 : 1;
    const int cap = 384 * k;
    const int base = t * 32;

    __shared__ int cnt[256];
    int local = 0;
#pragma unroll 4
    for (int i = 0; i < 32; i++) {
        int n = base + i;
        if ((n & 1) < k && g_te[n] == e) local++;
    }
    cnt[t] = local;
    __syncthreads();
    for (int off = 1; off < 256; off <<= 1) {
        int v = (t >= off) ? cnt[t - off] : 0;
        __syncthreads();
        cnt[t] += v;
        __syncthreads();
    }
    int total = cnt[255];
    int pos = cnt[t] - local;   // exclusive prefix

    float* disp = out;
    float* comb = out + COMB_OFF;
    const float* imp = out + IMP_OFF;

    for (int i = 0; i < 32; i++) {
        int n = base + i;
        int slot = n & 1;
        if (slot >= k || g_te[n] != e) continue;
        if (pos < cap) {
            int token = n >> 1;
            float tp0 = g_tp[token * 2 + 0];
            float tp1 = g_tp[token * 2 + 1];
            float denom = (k == 2) ? (tp0 + tp1 + 1e-8f) : (tp0 + 1e-8f);
            float pn = ((slot == 0) ? tp0 : tp1) / denom;
            float f = 1.f + ((imp[token] > 0.5f) ? 1.f : 0.f);
            long long off = (long long)token * NE * CAPM + (long long)e * CAPM + pos;
            disp[off] = 1.f;
            comb[off] = pn * f;
        }
        pos++;
    }
    if (t == 0) {
        float invN = 1.f / 4096.f;
        float invA = 1.f / (4096.f * (float)k);
        atomicAdd(&g_aux, (g_probsum[e] * invN) * ((float)total * invA) * (float)NE);
    }
}

__global__ void finalize_kernel(float* __restrict__ out) {
    out[AUX_OFF] = g_aux;
}

// ---------------------------------------------------------------------------
extern "C" void kernel_launch(void* const* d_in, const int* in_sizes, int n_in,
                              void* d_out, int out_size) {
    const float* X   = (const float*)d_in[0];
    const float* W1  = (const float*)d_in[1];
    const float* b1  = (const float*)d_in[2];
    const float* W2  = (const float*)d_in[3];
    const float* b2  = (const float*)d_in[4];
    const float* Wi1 = (const float*)d_in[5];
    const float* bi1 = (const float*)d_in[6];
    const float* Wi2 = (const float*)d_in[7];
    const float* bi2 = (const float*)d_in[8];
    const float* Wt1 = (const float*)d_in[9];
    const float* bt1 = (const float*)d_in[10];
    const float* Wt2 = (const float*)d_in[11];
    const float* bt2 = (const float*)d_in[12];
    float* out = (float*)d_out;

    float *H1p = nullptr, *Hip = nullptr;
    __nv_bfloat16 *A0p = nullptr, *A1p = nullptr, *B0p = nullptr, *B1p = nullptr;
    cudaGetSymbolAddress((void**)&H1p, g_H1);
    cudaGetSymbolAddress((void**)&Hip, g_Hi);
    cudaGetSymbolAddress((void**)&A0p, g_A0);
    cudaGetSymbolAddress((void**)&A1p, g_A1);
    cudaGetSymbolAddress((void**)&B0p, g_B0);
    cudaGetSymbolAddress((void**)&B1p, g_B1);

    cudaFuncSetAttribute(gemm_mma, cudaFuncAttributeMaxDynamicSharedMemorySize, SMEMT);

    static cudaStream_t s1 = nullptr;
    static cudaEvent_t ev0 = nullptr, ev1 = nullptr, evG = nullptr, evI = nullptr;
    if (!s1) {
        cudaStreamCreateWithFlags(&s1, cudaStreamNonBlocking);
        cudaEventCreateWithFlags(&ev0, cudaEventDisableTiming);
        cudaEventCreateWithFlags(&ev1, cudaEventDisableTiming);
        cudaEventCreateWithFlags(&evG, cudaEventDisableTiming);
        cudaEventCreateWithFlags(&evI, cudaEventDisableTiming);
    }

    // Submissions 1-4 (process launches 3-6; ncu -s 5 -c 1 captures gemm):
    convA_kernel<<<4096, 256>>>(X);
    convB_kernel<<<1536, 256>>>(W1, Wi1);
    init_small_kernel<<<1, 1024>>>();
    cudaEventRecord(ev0, 0);                        // fork point (after init)
    gemm_mma<<<dim3(NT / 128, BSZ / 64), 256, SMEMT>>>(A0p, A1p, B0p, B1p, b1, bi1, H1p, Hip);
    cudaEventRecord(evG, 0);

    // side stream: zero-fill + colmean run concurrently with gemm
    cudaStreamWaitEvent(s1, ev0, 0);
    zero_out_kernel<<<2048, 256, 0, s1>>>(out, 2 * D_SZ);
    colmean_kernel<<<64, 256, 0, s1>>>(X);
    cudaEventRecord(ev1, s1);

    // side stream: importance from Hi (concurrent with router)
    cudaStreamWaitEvent(s1, evG, 0);
    imp_kernel<<<BSZ / 8, 256, 0, s1>>>(Wi2, bi2, out + IMP_OFF);
    cudaEventRecord(evI, s1);

    // main: router
    router_kernel<<<BSZ / 8, 256>>>(W2, b2, out + RP_OFF);

    // join: zero/colmean + importance done before tk/scan
    cudaStreamWaitEvent(0, ev1, 0);
    cudaStreamWaitEvent(0, evI, 0);
    tk_matvec_kernel<<<256, 256>>>(Wt1, bt1, Wt2, bt2);
    scan_scatter16_kernel<<<NE, 256>>>(out);
    finalize_kernel<<<1, 1>>>(out);
}

// round 8
// speedup vs baseline: 2.5474x; 1.0001x over previous
#include <cuda_runtime.h>
#include <cuda_bf16.h>
#include <math.h>
#include <cstdint>

// Problem constants
#define BSZ   4096        // B*S tokens
#define HD    1024        // hidden
#define NE    16          // experts
#define CAPM  768         // CAP_MAX
#define HI2   512         // H/2
#define NT    1536        // combined N (W1 | Wi1)

static const long long D_SZ    = (long long)BSZ * NE * CAPM;       // 50331648
static const long long COMB_OFF= D_SZ;
static const long long RP_OFF  = 2 * D_SZ;                         // 100663296
static const long long AUX_OFF = RP_OFF + (long long)BSZ * NE;     // 100728832
static const long long IMP_OFF = AUX_OFF + 1;                      // 100728833

// Scratch (device globals; no cudaMalloc allowed)
__device__ float g_H1[(size_t)BSZ * HD];     // relu(X@W1+b1)   16MB
__device__ float g_Hi[(size_t)BSZ * HI2];    // relu(X@Wi1+bi1)  8MB
__device__ __nv_bfloat16 g_A0[(size_t)BSZ * HD];   // bf16 hi split of X
__device__ __nv_bfloat16 g_A1[(size_t)BSZ * HD];   // bf16 lo split of X
__device__ __nv_bfloat16 g_B0[(size_t)HD * NT];    // bf16 hi split of [W1|Wi1]
__device__ __nv_bfloat16 g_B1[(size_t)HD * NT];    // bf16 lo split
__device__ float g_avg[HD];                  // column sums of X
__device__ float g_impsum;                   // sum of importance
__device__ float g_probsum[NE];              // sum of router probs per expert
__device__ float g_tkl[2];                   // top-k predictor logits
__device__ float g_aux;                      // aux loss accumulator
__device__ float g_tp[BSZ * 2];              // top-2 probs
__device__ int   g_te[BSZ * 2];              // top-2 expert ids

// ===========================================================================
// PTX helpers (portable; nothing sm_103a-suffix-gated)
// ===========================================================================
__device__ __forceinline__ uint32_t smem_to_u32(const void* p) {
    uint32_t a;
    asm("{ .reg .u64 t; cvta.to.shared.u64 t, %1; cvt.u32.u64 %0, t; }" : "=r"(a) : "l"(p));
    return a;
}
#define LDSM4(d, a) \
    asm volatile("ldmatrix.sync.aligned.m8n8.x4.shared.b16 {%0,%1,%2,%3}, [%4];" \
        : "=r"((d)[0]), "=r"((d)[1]), "=r"((d)[2]), "=r"((d)[3]) : "r"(a))
#define LDSM4T(d, a) \
    asm volatile("ldmatrix.sync.aligned.m8n8.x4.trans.shared.b16 {%0,%1,%2,%3}, [%4];" \
        : "=r"((d)[0]), "=r"((d)[1]), "=r"((d)[2]), "=r"((d)[3]) : "r"(a))
#define MMA16816(c, a, b0, b1) \
    asm volatile("mma.sync.aligned.m16n8k16.row.col.f32.bf16.bf16.f32 " \
        "{%0,%1,%2,%3}, {%4,%5,%6,%7}, {%8,%9}, {%0,%1,%2,%3};" \
        : "+f"((c)[0]), "+f"((c)[1]), "+f"((c)[2]), "+f"((c)[3]) \
        : "r"((a)[0]), "r"((a)[1]), "r"((a)[2]), "r"((a)[3]), "r"(b0), "r"(b1))
#define CP16(s, g) \
    asm volatile("cp.async.cg.shared.global [%0], [%1], 16;" :: "r"(s), "l"(g))
#define CP_COMMIT() asm volatile("cp.async.commit_group;" ::: "memory")
#define CP_WAIT1()  asm volatile("cp.async.wait_group 1;" ::: "memory")
#define CP_WAIT0()  asm volatile("cp.async.wait_group 0;" ::: "memory")

// smem geometry (bytes): padded rows for conflict-free ldmatrix
#define AS_ROWB   80                     // 32 bf16 + pad -> 80B rows
#define BS_ROWB   272                    // 128 bf16 + pad -> 272B rows
#define A_SPLIT_B (64 * AS_ROWB)         // 5120
#define B_SPLIT_B (32 * BS_ROWB)         // 8704
#define B_OFF     (2 * A_SPLIT_B)        // 10240
#define BUF_B     (B_OFF + 2 * B_SPLIT_B)// 27648
#define STAGES    3
#define SMEMT     (STAGES * BUF_B)       // 82944

// ===========================================================================
// fused HMMA bf16-split GEMM: [H1|Hi] = relu(X @ [W1|Wi1] + [b1|bi1])
// grid (12, 64), 256 threads; block tile 64x128, BK=32, warp tile 32x32.
// 3-stage cp.async pipeline, ONE barrier per k-iter, occ=2.
// Per k16-step: batch ALL 8 LDSMs, then an unbroken 24-MMA stream.
// 3 products: A0B0 + A1B0 + A0B1.
// ===========================================================================
__global__ __launch_bounds__(256, 2)
void gemm_mma(const __nv_bfloat16* __restrict__ A0g, const __nv_bfloat16* __restrict__ A1g,
              const __nv_bfloat16* __restrict__ B0g, const __nv_bfloat16* __restrict__ B1g,
              const float* __restrict__ b1, const float* __restrict__ bi1,
              float* __restrict__ H1, float* __restrict__ Hi) {
    extern __shared__ char smem[];
    const uint32_t sb = smem_to_u32(smem);
    const int tid = threadIdx.x, wid = tid >> 5, lane = tid & 31;
    const int m0 = blockIdx.y * 64;
    const int n0 = blockIdx.x * 128;

    // ---- global->smem loaders (cp.async): A 2x16B, B 4x16B per thread ----
    const int ar = tid >> 2, acq = tid & 3;             // A: row 0..63, 16B chunk 0..3
    const int br = tid >> 3, bcq = tid & 7;             // B: row 0..31, 32B chunk 0..7
    const __nv_bfloat16* A0p = A0g + (size_t)(m0 + ar) * HD + acq * 8;
    const __nv_bfloat16* A1p = A1g + (size_t)(m0 + ar) * HD + acq * 8;
    const __nv_bfloat16* B0p = B0g + (size_t)br * NT + n0 + bcq * 16;
    const __nv_bfloat16* B1p = B1g + (size_t)br * NT + n0 + bcq * 16;
    const uint32_t asw = sb + (uint32_t)ar * AS_ROWB + acq * 16;
    const uint32_t bsw = sb + B_OFF + (uint32_t)br * BS_ROWB + bcq * 32;

    auto issue = [&](int it, int stg) {
        const uint32_t a = asw + stg * BUF_B;
        CP16(a,             A0p + it * 32);
        CP16(a + A_SPLIT_B, A1p + it * 32);
        const uint32_t b = bsw + stg * BUF_B;
        const __nv_bfloat16* pb0 = B0p + (size_t)it * 32 * NT;
        const __nv_bfloat16* pb1 = B1p + (size_t)it * 32 * NT;
        CP16(b,                  pb0);
        CP16(b + 16,             pb0 + 8);
        CP16(b + B_SPLIT_B,      pb1);
        CP16(b + B_SPLIT_B + 16, pb1 + 8);
        CP_COMMIT();
    };

    // ---- per-warp ldmatrix base addresses ----
    const int wm = wid >> 2, wn = wid & 3;              // 2 x 4 warp grid
    const int mbase = wm * 32, nbase = wn * 32;
    const int l8 = lane & 7, lb8 = (lane >> 3) & 1, lhi = lane >> 4;
    const uint32_t aAddr = sb + (uint32_t)(mbase + l8 + 8 * lb8) * AS_ROWB + lhi * 16;
    const uint32_t bAddr = sb + B_OFF + (uint32_t)(l8 + 8 * lb8) * BS_ROWB
                         + (uint32_t)(nbase + lhi * 8) * 2;

    float acc[2][4][4];
#pragma unroll
    for (int i = 0; i < 2; i++)
#pragma unroll
        for (int j = 0; j < 4; j++)
#pragma unroll
            for (int c = 0; c < 4; c++) acc[i][j][c] = 0.f;

    issue(0, 0);
    issue(1, 1);

    int stg = 0;
    for (int it = 0; it < 32; it++) {
        if (it < 30) CP_WAIT1(); else CP_WAIT0();
        __syncthreads();                 // protects stage reuse AND data-ready
        if (it < 30) issue(it + 2, (it + 2) % STAGES);

        const uint32_t aB = aAddr + stg * BUF_B;
        const uint32_t bB = bAddr + stg * BUF_B;
#pragma unroll
        for (int ks = 0; ks < 2; ks++) {
            const uint32_t aK = aB + ks * 32;            // 16 k-elems = 32 bytes
            const uint32_t bK = bB + ks * 16 * BS_ROWB;  // 16 k-rows
            uint32_t a0f[2][4], a1f[2][4], b0f[2][4], b1f[2][4];
            // --- batch ALL fragment loads (first-consumed loaded first) ---
#pragma unroll
            for (int nt = 0; nt < 2; nt++) LDSM4T(b0f[nt], bK + nt * 32);
#pragma unroll
            for (int ti = 0; ti < 2; ti++) LDSM4(a0f[ti], aK + ti * 16 * AS_ROWB);
#pragma unroll
            for (int ti = 0; ti < 2; ti++) LDSM4(a1f[ti], aK + A_SPLIT_B + ti * 16 * AS_ROWB);
#pragma unroll
            for (int nt = 0; nt < 2; nt++) LDSM4T(b1f[nt], bK + B_SPLIT_B + nt * 32);
            // --- unbroken 24-MMA stream ---
#pragma unroll
            for (int ti = 0; ti < 2; ti++)
#pragma unroll
                for (int nj = 0; nj < 4; nj++)
                    MMA16816(acc[ti][nj], a0f[ti], b0f[nj >> 1][(nj & 1) * 2], b0f[nj >> 1][(nj & 1) * 2 + 1]);
#pragma unroll
            for (int ti = 0; ti < 2; ti++)
#pragma unroll
                for (int nj = 0; nj < 4; nj++)
                    MMA16816(acc[ti][nj], a1f[ti], b0f[nj >> 1][(nj & 1) * 2], b0f[nj >> 1][(nj & 1) * 2 + 1]);
#pragma unroll
            for (int ti = 0; ti < 2; ti++)
#pragma unroll
                for (int nj = 0; nj < 4; nj++)
                    MMA16816(acc[ti][nj], a0f[ti], b1f[nj >> 1][(nj & 1) * 2], b1f[nj >> 1][(nj & 1) * 2 + 1]);
        }
        stg = (stg == STAGES - 1) ? 0 : stg + 1;
    }

    // ---- epilogue: bias + relu, direct global stores ----
    const bool isH1 = (n0 < HD);
    float* dst = isH1 ? H1 : Hi;
    const int stride = isH1 ? HD : HI2;
    const int nadj = isH1 ? n0 : (n0 - HD);
    const float* bias = isH1 ? b1 : bi1;
#pragma unroll
    for (int ti = 0; ti < 2; ti++) {
        const int r0 = m0 + mbase + ti * 16 + (lane >> 2);
#pragma unroll
        for (int nj = 0; nj < 4; nj++) {
            const int cn = nadj + nbase + nj * 8 + (lane & 3) * 2;
            const float bx = __ldg(bias + cn), by = __ldg(bias + cn + 1);
            float2 v0, v1;
            v0.x = fmaxf(acc[ti][nj][0] + bx, 0.f);
            v0.y = fmaxf(acc[ti][nj][1] + by, 0.f);
            v1.x = fmaxf(acc[ti][nj][2] + bx, 0.f);
            v1.y = fmaxf(acc[ti][nj][3] + by, 0.f);
            *(float2*)(dst + (size_t)r0 * stride + cn)       = v0;
            *(float2*)(dst + (size_t)(r0 + 8) * stride + cn) = v1;
        }
    }
}

// ===========================================================================
// pre-pass converters: fp32 -> bf16 split pair
// ===========================================================================
__device__ __forceinline__ void split_bf16(float f, __nv_bfloat16& h0, __nv_bfloat16& h1) {
    h0 = __float2bfloat16_rn(f);
    h1 = __float2bfloat16_rn(f - __bfloat162float(h0));
}

__global__ __launch_bounds__(256)
void convA_kernel(const float* __restrict__ X) {
    size_t i = (size_t)blockIdx.x * 256 + threadIdx.x;   // over 1M float4
    float4 v = ((const float4*)X)[i];
    __nv_bfloat162 a0, a1, b0, b1;
    split_bf16(v.x, a0.x, a1.x); split_bf16(v.y, a0.y, a1.y);
    split_bf16(v.z, b0.x, b1.x); split_bf16(v.w, b0.y, b1.y);
    ((__nv_bfloat162*)g_A0)[2 * i]     = a0;
    ((__nv_bfloat162*)g_A0)[2 * i + 1] = b0;
    ((__nv_bfloat162*)g_A1)[2 * i]     = a1;
    ((__nv_bfloat162*)g_A1)[2 * i + 1] = b1;
}

__global__ __launch_bounds__(256)
void convB_kernel(const float* __restrict__ W1, const float* __restrict__ Wi1) {
    size_t i = (size_t)blockIdx.x * 256 + threadIdx.x;   // over 1024*1536/4 float4
    int r = (int)(i / 384);
    int c = (int)(i % 384) * 4;
    float4 v = (c < HD) ? *(const float4*)(W1 + (size_t)r * HD + c)
                        : *(const float4*)(Wi1 + (size_t)r * HI2 + c - HD);
    __nv_bfloat162 a0, a1, b0, b1;
    split_bf16(v.x, a0.x, a1.x); split_bf16(v.y, a0.y, a1.y);
    split_bf16(v.z, b0.x, b1.x); split_bf16(v.w, b0.y, b1.y);
    ((__nv_bfloat162*)g_B0)[2 * i]     = a0;
    ((__nv_bfloat162*)g_B0)[2 * i + 1] = b0;
    ((__nv_bfloat162*)g_B1)[2 * i]     = a1;
    ((__nv_bfloat162*)g_B1)[2 * i + 1] = b1;
}

// ===========================================================================
// zero dispatch+combine region; streaming (evict-first) stores keep L2 clean
__global__ void zero_out_kernel(float* __restrict__ out, long long n) {
    long long stride = (long long)gridDim.x * blockDim.x;
    long long i = (long long)blockIdx.x * blockDim.x + threadIdx.x;
    long long n4 = n >> 2;
    float4 z = make_float4(0.f, 0.f, 0.f, 0.f);
    for (long long j = i; j < n4; j += stride)
        __stcs(&((float4*)out)[j], z);
}

__global__ void init_small_kernel() {
    int t = threadIdx.x;
    if (t < HD) g_avg[t] = 0.f;
    if (t < NE) g_probsum[t] = 0.f;
    if (t == 0) { g_impsum = 0.f; g_aux = 0.f; }
    if (t < 2) g_tkl[t] = 0.f;
}

// ---------------------------------------------------------------------------
// importance = sigmoid(Hi @ Wi2 + bi2); one warp per token
__global__ __launch_bounds__(256)
void imp_kernel(const float* __restrict__ Wi2, const float* __restrict__ bi2,
                float* __restrict__ out_imp) {
    __shared__ float w[HI2];
    int t = threadIdx.x;
    w[t] = Wi2[t];
    w[t + 256] = Wi2[t + 256];
    __syncthreads();
    int warp = t >> 5, lane = t & 31;
    int token = blockIdx.x * 8 + warp;
    const float* h = g_Hi + (size_t)token * HI2;
    float acc = 0.f;
#pragma unroll
    for (int i = 0; i < HI2 / 32; i++)
        acc += h[lane + 32 * i] * w[lane + 32 * i];
#pragma unroll
    for (int o = 16; o; o >>= 1) acc += __shfl_xor_sync(0xffffffffu, acc, o);
    if (lane == 0) {
        float v = 1.f / (1.f + expf(-(acc + bi2[0])));
        out_imp[token] = v;
        atomicAdd(&g_impsum, v);
    }
}

// column sums of X -> g_avg
__global__ __launch_bounds__(256)
void colmean_kernel(const float* __restrict__ X) {
    int t = threadIdx.x;
    int r0 = blockIdx.x * 64;
    float4 s = make_float4(0.f, 0.f, 0.f, 0.f);
    for (int r = r0; r < r0 + 64; r++) {
        float4 v = ((const float4*)X)[(size_t)r * 256 + t];
        s.x += v.x; s.y += v.y; s.z += v.z; s.w += v.w;
    }
    atomicAdd(&g_avg[t * 4 + 0], s.x);
    atomicAdd(&g_avg[t * 4 + 1], s.y);
    atomicAdd(&g_avg[t * 4 + 2], s.z);
    atomicAdd(&g_avg[t * 4 + 3], s.w);
}

// top-k predictor matvec: block j computes hidden unit j, accumulates logits
__global__ __launch_bounds__(256)
void tk_matvec_kernel(const float* __restrict__ Wt1, const float* __restrict__ bt1,
                      const float* __restrict__ Wt2, const float* __restrict__ bt2) {
    int j = blockIdx.x, t = threadIdx.x;
    const float invN = 1.f / 4096.f;
    float acc = 0.f;
    for (int i = t; i < HD; i += 256)
        acc += (g_avg[i] * invN) * Wt1[(size_t)i * 256 + j];
    __shared__ float s[256];
    s[t] = acc;
    __syncthreads();
    for (int o = 128; o; o >>= 1) {
        if (t < o) s[t] += s[t + o];
        __syncthreads();
    }
    if (t == 0) {
        float a = s[0] + (g_impsum * invN) * Wt1[(size_t)HD * 256 + j] + bt1[j];
        float h = fmaxf(a, 0.f);
        atomicAdd(&g_tkl[0], h * Wt2[j * 2 + 0]);
        atomicAdd(&g_tkl[1], h * Wt2[j * 2 + 1]);
        if (j == 0) {
            atomicAdd(&g_tkl[0], bt2[0]);
            atomicAdd(&g_tkl[1], bt2[1]);
        }
    }
}

// ---------------------------------------------------------------------------
// router: logits = H1 @ W2 + b2 -> softmax -> probs + top-2. One warp/token.
__global__ __launch_bounds__(256)
void router_kernel(const float* __restrict__ W2, const float* __restrict__ b2,
                   float* __restrict__ out_rp) {
    __shared__ float ps[NE];
    int t = threadIdx.x, warp = t >> 5, lane = t & 31;
    if (t < NE) ps[t] = 0.f;
    __syncthreads();
    int token = blockIdx.x * 8 + warp;
    const float* h = g_H1 + (size_t)token * HD;
    float acc[NE];
#pragma unroll
    for (int e = 0; e < NE; e++) acc[e] = 0.f;
    for (int i = 0; i < HD / 32; i++) {
        int k = lane + 32 * i;
        float hv = h[k];
        const float4* w = (const float4*)(W2 + (size_t)k * NE);
        float4 w0 = __ldg(w + 0), w1 = __ldg(w + 1), w2 = __ldg(w + 2), w3 = __ldg(w + 3);
        acc[0]  += hv * w0.x; acc[1]  += hv * w0.y; acc[2]  += hv * w0.z; acc[3]  += hv * w0.w;
        acc[4]  += hv * w1.x; acc[5]  += hv * w1.y; acc[6]  += hv * w1.z; acc[7]  += hv * w1.w;
        acc[8]  += hv * w2.x; acc[9]  += hv * w2.y; acc[10] += hv * w2.z; acc[11] += hv * w2.w;
        acc[12] += hv * w3.x; acc[13] += hv * w3.y; acc[14] += hv * w3.z; acc[15] += hv * w3.w;
    }
#pragma unroll
    for (int e = 0; e < NE; e++)
#pragma unroll
        for (int o = 16; o; o >>= 1) acc[e] += __shfl_xor_sync(0xffffffffu, acc[e], o);

    if (lane == 0) {
        float p[NE];
        float mx = -1e30f;
#pragma unroll
        for (int e = 0; e < NE; e++) { p[e] = acc[e] + b2[e]; mx = fmaxf(mx, p[e]); }
        float sum = 0.f;
#pragma unroll
        for (int e = 0; e < NE; e++) { p[e] = expf(p[e] - mx); sum += p[e]; }
        float inv = 1.f / sum;
#pragma unroll
        for (int e = 0; e < NE; e++) p[e] *= inv;
#pragma unroll
        for (int e = 0; e < NE; e++) {
            out_rp[(size_t)token * NE + e] = p[e];
            atomicAdd(&ps[e], p[e]);
        }
        int e0 = 0;
#pragma unroll
        for (int e = 1; e < NE; e++) if (p[e] > p[e0]) e0 = e;
        int best = -1; float bv = -1.f;
#pragma unroll
        for (int e = 0; e < NE; e++) {
            if (e == e0) continue;
            if (p[e] > bv) { bv = p[e]; best = e; }
        }
        g_tp[token * 2 + 0] = p[e0];
        g_tp[token * 2 + 1] = p[best];
        g_te[token * 2 + 0] = e0;
        g_te[token * 2 + 1] = best;
    }
    __syncthreads();
    if (t < NE) atomicAdd(&g_probsum[t], ps[t]);
}

// ---------------------------------------------------------------------------
// per-expert parallel scan + scatter: one block per expert (grid = 16)
__global__ __launch_bounds__(256)
void scan_scatter16_kernel(float* __restrict__ out) {
    const int e = blockIdx.x;
    const int t = threadIdx.x;
    const int k = (g_tkl[1] > g_tkl[0]) ? 2 : 1;
    const int cap = 384 * k;
    const int base = t * 32;

    __shared__ int cnt[256];
    int local = 0;
#pragma unroll 4
    for (int i = 0; i < 32; i++) {
        int n = base + i;
        if ((n & 1) < k && g_te[n] == e) local++;
    }
    cnt[t] = local;
    __syncthreads();
    for (int off = 1; off < 256; off <<= 1) {
        int v = (t >= off) ? cnt[t - off] : 0;
        __syncthreads();
        cnt[t] += v;
        __syncthreads();
    }
    int total = cnt[255];
    int pos = cnt[t] - local;   // exclusive prefix

    float* disp = out;
    float* comb = out + COMB_OFF;
    const float* imp = out + IMP_OFF;

    for (int i = 0; i < 32; i++) {
        int n = base + i;
        int slot = n & 1;
        if (slot >= k || g_te[n] != e) continue;
        if (pos < cap) {
            int token = n >> 1;
            float tp0 = g_tp[token * 2 + 0];
            float tp1 = g_tp[token * 2 + 1];
            float denom = (k == 2) ? (tp0 + tp1 + 1e-8f) : (tp0 + 1e-8f);
            float pn = ((slot == 0) ? tp0 : tp1) / denom;
            float f = 1.f + ((imp[token] > 0.5f) ? 1.f : 0.f);
            long long off = (long long)token * NE * CAPM + (long long)e * CAPM + pos;
            disp[off] = 1.f;
            comb[off] = pn * f;
        }
        pos++;
    }
    if (t == 0) {
        float invN = 1.f / 4096.f;
        float invA = 1.f / (4096.f * (float)k);
        atomicAdd(&g_aux, (g_probsum[e] * invN) * ((float)total * invA) * (float)NE);
    }
}

__global__ void finalize_kernel(float* __restrict__ out) {
    out[AUX_OFF] = g_aux;
}

// ---------------------------------------------------------------------------
extern "C" void kernel_launch(void* const* d_in, const int* in_sizes, int n_in,
                              void* d_out, int out_size) {
    const float* X   = (const float*)d_in[0];
    const float* W1  = (const float*)d_in[1];
    const float* b1  = (const float*)d_in[2];
    const float* W2  = (const float*)d_in[3];
    const float* b2  = (const float*)d_in[4];
    const float* Wi1 = (const float*)d_in[5];
    const float* bi1 = (const float*)d_in[6];
    const float* Wi2 = (const float*)d_in[7];
    const float* bi2 = (const float*)d_in[8];
    const float* Wt1 = (const float*)d_in[9];
    const float* bt1 = (const float*)d_in[10];
    const float* Wt2 = (const float*)d_in[11];
    const float* bt2 = (const float*)d_in[12];
    float* out = (float*)d_out;

    float *H1p = nullptr, *Hip = nullptr;
    __nv_bfloat16 *A0p = nullptr, *A1p = nullptr, *B0p = nullptr, *B1p = nullptr;
    cudaGetSymbolAddress((void**)&H1p, g_H1);
    cudaGetSymbolAddress((void**)&Hip, g_Hi);
    cudaGetSymbolAddress((void**)&A0p, g_A0);
    cudaGetSymbolAddress((void**)&A1p, g_A1);
    cudaGetSymbolAddress((void**)&B0p, g_B0);
    cudaGetSymbolAddress((void**)&B1p, g_B1);

    cudaFuncSetAttribute(gemm_mma, cudaFuncAttributeMaxDynamicSharedMemorySize, SMEMT);

    static cudaStream_t s1 = nullptr;
    static cudaEvent_t ev0 = nullptr, ev1 = nullptr, evG = nullptr, evI = nullptr;
    if (!s1) {
        cudaStreamCreateWithFlags(&s1, cudaStreamNonBlocking);
        cudaEventCreateWithFlags(&ev0, cudaEventDisableTiming);
        cudaEventCreateWithFlags(&ev1, cudaEventDisableTiming);
        cudaEventCreateWithFlags(&evG, cudaEventDisableTiming);
        cudaEventCreateWithFlags(&evI, cudaEventDisableTiming);
    }

    // Submissions 1-4 (process launches 3-6; ncu -s 5 -c 1 captures gemm):
    convA_kernel<<<4096, 256>>>(X);
    convB_kernel<<<1536, 256>>>(W1, Wi1);
    init_small_kernel<<<1, 1024>>>();
    cudaEventRecord(ev0, 0);                        // fork point (after init)
    gemm_mma<<<dim3(NT / 128, BSZ / 64), 256, SMEMT>>>(A0p, A1p, B0p, B1p, b1, bi1, H1p, Hip);
    cudaEventRecord(evG, 0);

    // side stream: zero-fill + colmean run concurrently with gemm
    cudaStreamWaitEvent(s1, ev0, 0);
    zero_out_kernel<<<2048, 256, 0, s1>>>(out, 2 * D_SZ);
    colmean_kernel<<<64, 256, 0, s1>>>(X);
    cudaEventRecord(ev1, s1);

    // side stream: importance from Hi (concurrent with router)
    cudaStreamWaitEvent(s1, evG, 0);
    imp_kernel<<<BSZ / 8, 256, 0, s1>>>(Wi2, bi2, out + IMP_OFF);
    cudaEventRecord(evI, s1);

    // main: router
    router_kernel<<<BSZ / 8, 256>>>(W2, b2, out + RP_OFF);

    // join: zero/colmean + importance done before tk/scan
    cudaStreamWaitEvent(0, ev1, 0);
    cudaStreamWaitEvent(0, evI, 0);
    tk_matvec_kernel<<<256, 256>>>(Wt1, bt1, Wt2, bt2);
    scan_scatter16_kernel<<<NE, 256>>>(out);
    finalize_kernel<<<1, 1>>>(out);
}